// round 11
// baseline (speedup 1.0000x reference)
#include <cuda_runtime.h>
#include <cstdint>

#define N      2048
#define DM     512
#define HH     8
#define NN     (N * N)

typedef unsigned long long ull;

// ---------------- device scratch ----------------
__device__ float    g_q[DM * N];
__device__ float    g_k[DM * N];
__device__ float    g_v[DM * N];
__device__ float    g_x[DM * N];
__device__ float    g_E[HH * NN];
__device__ float    g_mean[NN];          // sum over h of raw scores
__device__ float    g_psu[HH * N * 16];
__device__ float    g_psm[HH * N * 16];
__device__ float    g_rinv[HH * N];
__device__ unsigned g_smin_enc;
__device__ unsigned g_mask_or;

// ---------------- helpers ----------------
__device__ __forceinline__ unsigned enc_f(float x) {
    unsigned u = __float_as_uint(x);
    return (u & 0x80000000u) ? ~u : (u | 0x80000000u);
}
__device__ __forceinline__ float dec_f(unsigned u) {
    return (u & 0x80000000u) ? __uint_as_float(u & 0x7FFFFFFFu)
                             : __uint_as_float(~u);
}
__device__ __forceinline__ float mask_not(const void* mask, int i, unsigned o) {
    bool mv;
    if (o == 0x3F800000u)      mv = ((const float*)mask)[i] != 0.0f;
    else if (o == 1u)          mv = ((const int*)mask)[i] != 0;
    else                       mv = ((const unsigned char*)mask)[i] != 0;
    return mv ? 0.0f : 1.0f;
}
__device__ __forceinline__ float4 mask_not4(const void* mask, int i, unsigned o) {
    float4 r;
    if (o == 0x3F800000u) {
        float4 m = *(const float4*)((const float*)mask + i);
        r.x = m.x != 0.0f ? 0.f : 1.f; r.y = m.y != 0.0f ? 0.f : 1.f;
        r.z = m.z != 0.0f ? 0.f : 1.f; r.w = m.w != 0.0f ? 0.f : 1.f;
    } else if (o == 1u) {
        int4 m = *(const int4*)((const int*)mask + i);
        r.x = m.x ? 0.f : 1.f; r.y = m.y ? 0.f : 1.f;
        r.z = m.z ? 0.f : 1.f; r.w = m.w ? 0.f : 1.f;
    } else {
        uchar4 m = *(const uchar4*)((const unsigned char*)mask + i);
        r.x = m.x ? 0.f : 1.f; r.y = m.y ? 0.f : 1.f;
        r.z = m.z ? 0.f : 1.f; r.w = m.w ? 0.f : 1.f;
    }
    return r;
}
__device__ __forceinline__ void ffma2(ull& d, ull a, ull b) {
    asm("fma.rn.f32x2 %0, %1, %2, %0;" : "+l"(d) : "l"(a), "l"(b));
}
__device__ __forceinline__ ull pk2(float x, float y) {
    ull r; asm("mov.b64 %0, {%1, %2};" : "=l"(r) : "f"(x), "f"(y)); return r;
}
__device__ __forceinline__ float2 up2(ull p) {
    float2 r; asm("mov.b64 {%0, %1}, %2;" : "=f"(r.x), "=f"(r.y) : "l"(p)); return r;
}
__device__ __forceinline__ uint32_t smem_u32(const void* p) {
    uint32_t a;
    asm("{ .reg .u64 t; cvta.to.shared.u64 t, %1; cvt.u32.u64 %0, t; }"
        : "=r"(a) : "l"(p));
    return a;
}
// pack (a,b) -> bf16x2 with bf16(a) in low half
__device__ __forceinline__ unsigned pkbf(float a, float b) {
    unsigned r; asm("cvt.rn.bf16x2.f32 %0, %1, %2;" : "=r"(r) : "f"(b), "f"(a));
    return r;
}
__device__ __forceinline__ void ldsm4(unsigned* r, uint32_t a) {
    asm volatile("ldmatrix.sync.aligned.m8n8.x4.shared.b16 {%0,%1,%2,%3}, [%4];"
        : "=r"(r[0]), "=r"(r[1]), "=r"(r[2]), "=r"(r[3]) : "r"(a));
}
__device__ __forceinline__ void mma16816(float* c, const unsigned* a,
                                         unsigned b0, unsigned b1) {
    asm volatile(
        "mma.sync.aligned.m16n8k16.row.col.f32.bf16.bf16.f32 "
        "{%0,%1,%2,%3}, {%4,%5,%6,%7}, {%8,%9}, {%0,%1,%2,%3};"
        : "+f"(c[0]), "+f"(c[1]), "+f"(c[2]), "+f"(c[3])
        : "r"(a[0]), "r"(a[1]), "r"(a[2]), "r"(a[3]), "r"(b0), "r"(b1));
}

// ---------------- small kernels ----------------
__global__ void init_kernel() { g_smin_enc = 0xFFFFFFFFu; g_mask_or = 0u; }

__global__ void mask_detect_kernel(const unsigned* __restrict__ m) {
    __shared__ unsigned sh[256];
    unsigned acc = 0;
    const int total = NN / 4;
    for (int i = blockIdx.x * blockDim.x + threadIdx.x; i < total;
         i += gridDim.x * blockDim.x) acc |= m[i];
    sh[threadIdx.x] = acc;
    __syncthreads();
    for (int s = 128; s > 0; s >>= 1) {
        if (threadIdx.x < s) sh[threadIdx.x] |= sh[threadIdx.x + s];
        __syncthreads();
    }
    if (threadIdx.x == 0) atomicOr(&g_mask_or, sh[0]);
}

// ---------------- FFMA2 GEMM core (qkv / merge) ----------------
__device__ __forceinline__ void gemm16(const float (*__restrict__ As)[64],
                                       const float (*__restrict__ Bs)[132],
                                       ull acc[8][4], int tx, int ty) {
    #pragma unroll
    for (int k = 0; k < 16; k++) {
        float4 a0 = *(const float4*)&As[k][ty * 8];
        float4 a1 = *(const float4*)&As[k][ty * 8 + 4];
        float4 b0 = *(const float4*)&Bs[k][tx * 4];
        float4 b1 = *(const float4*)&Bs[k][64 + tx * 4];
        ull pb0 = pk2(b0.x, b0.y), pb1 = pk2(b0.z, b0.w);
        ull pb2 = pk2(b1.x, b1.y), pb3 = pk2(b1.z, b1.w);
        float av[8] = {a0.x, a0.y, a0.z, a0.w, a1.x, a1.y, a1.z, a1.w};
        #pragma unroll
        for (int i = 0; i < 8; i++) {
            ull pa = pk2(av[i], av[i]);
            ffma2(acc[i][0], pa, pb0);
            ffma2(acc[i][1], pa, pb1);
            ffma2(acc[i][2], pa, pb2);
            ffma2(acc[i][3], pa, pb3);
        }
    }
}

__global__ __launch_bounds__(128) void qkv_kernel(
    const float* __restrict__ Wq, const float* __restrict__ Wk,
    const float* __restrict__ Wv, const float* __restrict__ bq,
    const float* __restrict__ bk, const float* __restrict__ bv,
    const float* __restrict__ Xq, const float* __restrict__ Xk,
    const float* __restrict__ Xv,
    float* __restrict__ Oq, float* __restrict__ Ok, float* __restrict__ Ov)
{
    const float *W, *Bv_, *X;
    float* O;
    if (blockIdx.z == 0)      { W = Wq; Bv_ = bq; X = Xq; O = Oq; }
    else if (blockIdx.z == 1) { W = Wk; Bv_ = bk; X = Xk; O = Ok; }
    else                      { W = Wv; Bv_ = bv; X = Xv; O = Ov; }

    __shared__ float As[2][16][64];
    __shared__ float Bs[2][16][132];
    const int tid = threadIdx.x, tx = tid & 15, ty = tid >> 4;
    const int n0 = blockIdx.x * 128, m0 = blockIdx.y * 64;

    ull acc[8][4];
    #pragma unroll
    for (int i = 0; i < 8; i++)
        #pragma unroll
        for (int j = 0; j < 4; j++) acc[i][j] = 0ull;

    const int ao = tid >> 1, ac = (tid & 1) * 8;
    const float* Ap = W + (m0 + ao) * DM + ac;
    const int brow = tid >> 5, bc4 = tid & 31;
    const float* Bp = X + brow * N + n0 + bc4 * 4;

    float4 ra0, ra1, rb[4];
    ra0 = *(const float4*)(Ap);
    ra1 = *(const float4*)(Ap + 4);
    #pragma unroll
    for (int i = 0; i < 4; i++)
        rb[i] = *(const float4*)(Bp + (i * 4) * N);
    {
        As[0][ac + 0][ao] = ra0.x; As[0][ac + 1][ao] = ra0.y;
        As[0][ac + 2][ao] = ra0.z; As[0][ac + 3][ao] = ra0.w;
        As[0][ac + 4][ao] = ra1.x; As[0][ac + 5][ao] = ra1.y;
        As[0][ac + 6][ao] = ra1.z; As[0][ac + 7][ao] = ra1.w;
        #pragma unroll
        for (int i = 0; i < 4; i++)
            *(float4*)&Bs[0][brow + i * 4][bc4 * 4] = rb[i];
    }
    __syncthreads();

    const int KT = DM / 16;
    for (int kt = 0; kt < KT; kt++) {
        const int s = kt & 1;
        if (kt + 1 < KT) {
            const int c0 = (kt + 1) * 16;
            ra0 = *(const float4*)(Ap + c0);
            ra1 = *(const float4*)(Ap + c0 + 4);
            #pragma unroll
            for (int i = 0; i < 4; i++)
                rb[i] = *(const float4*)(Bp + (c0 + i * 4) * N);
        }
        gemm16(As[s], Bs[s], acc, tx, ty);
        if (kt + 1 < KT) {
            const int d = s ^ 1;
            As[d][ac + 0][ao] = ra0.x; As[d][ac + 1][ao] = ra0.y;
            As[d][ac + 2][ao] = ra0.z; As[d][ac + 3][ao] = ra0.w;
            As[d][ac + 4][ao] = ra1.x; As[d][ac + 5][ao] = ra1.y;
            As[d][ac + 6][ao] = ra1.z; As[d][ac + 7][ao] = ra1.w;
            #pragma unroll
            for (int i = 0; i < 4; i++)
                *(float4*)&Bs[d][brow + i * 4][bc4 * 4] = rb[i];
        }
        __syncthreads();
    }

    #pragma unroll
    for (int i = 0; i < 8; i++) {
        float bias = Bv_[m0 + ty * 8 + i];
        float2 v0 = up2(acc[i][0]), v1 = up2(acc[i][1]);
        float2 v2 = up2(acc[i][2]), v3 = up2(acc[i][3]);
        float4 o0 = {v0.x + bias, v0.y + bias, v1.x + bias, v1.y + bias};
        float4 o1 = {v2.x + bias, v2.y + bias, v3.x + bias, v3.y + bias};
        float* row = O + (m0 + ty * 8 + i) * N + n0;
        *(float4*)(row + tx * 4) = o0;
        *(float4*)(row + 64 + tx * 4) = o1;
    }
}

// -------- scores: all-heads 128n x 128m per CTA, mma.sync 3-pass ----------
// dyn smem: QH QL KH KL (4 x 18432) | TB f32 128x132 | MB f32 128x132
#define SPITCH 144
#define SC_QH 0
#define SC_QL 18432
#define SC_KH 36864
#define SC_KL 55296
#define SC_TB 73728
#define SC_MB 141312
#define SC_TOT 208896

__global__ __launch_bounds__(256) void scores_mma_kernel(
    const float* __restrict__ qg, const float* __restrict__ kg,
    const void* __restrict__ mask,
    float* __restrict__ E, float* __restrict__ meanb)
{
    extern __shared__ char dsm[];
    __shared__ float red[8];
    float* TBf = (float*)(dsm + SC_TB);
    float* MBf = (float*)(dsm + SC_MB);
    const int tid = threadIdx.x, lane = tid & 31, w = tid >> 5;
    const int wn = w & 3, wm = w >> 2;
    const int m0g = blockIdx.x * 128, n0g = blockIdx.y * 128;
    const uint32_t sb = smem_u32(dsm);
    const unsigned mo = g_mask_or;
    const int r8 = lane & 7, jm = lane >> 3;
    const int l8 = lane & 7, l8g = lane >> 3;
    float lmin = 3.0e38f;

    for (int h = 0; h < HH; h++) {
        // stage q/k as bf16 hi/lo, rows = n(or m), cols = d, pitch 144B
        {
            const int n = tid & 127, dg = tid >> 7;
            #pragma unroll 4
            for (int i = 0; i < 16; i++) {
                const int d = i * 4 + dg * 2;
                float q0 = qg[(d * HH + h) * N + n0g + n];
                float q1 = qg[((d + 1) * HH + h) * N + n0g + n];
                float k0 = kg[(d * HH + h) * N + m0g + n];
                float k1 = kg[((d + 1) * HH + h) * N + m0g + n];
                unsigned qh = pkbf(q0, q1);
                unsigned kh = pkbf(k0, k1);
                unsigned ql = pkbf(q0 - __uint_as_float(qh << 16),
                                   q1 - __uint_as_float(qh & 0xFFFF0000u));
                unsigned kl = pkbf(k0 - __uint_as_float(kh << 16),
                                   k1 - __uint_as_float(kh & 0xFFFF0000u));
                const int off = n * SPITCH + d * 2;
                *(unsigned*)(dsm + SC_QH + off) = qh;
                *(unsigned*)(dsm + SC_QL + off) = ql;
                *(unsigned*)(dsm + SC_KH + off) = kh;
                *(unsigned*)(dsm + SC_KL + off) = kl;
            }
        }
        __syncthreads();

        float c[2][8][4];
        #pragma unroll
        for (int a = 0; a < 2; a++)
            #pragma unroll
            for (int b = 0; b < 8; b++)
                #pragma unroll
                for (int d = 0; d < 4; d++) c[a][b][d] = 0.0f;

        #pragma unroll
        for (int ks = 0; ks < 4; ks++) {
            unsigned ah[2][4], al[2][4], bh[4][4], bl[4][4];
            #pragma unroll
            for (int na = 0; na < 2; na++) {
                uint32_t ad = sb + SC_QH
                    + (wn * 32 + na * 16 + (jm & 1) * 8 + r8) * SPITCH
                    + ks * 32 + (jm >> 1) * 16;
                ldsm4(ah[na], ad);
                ldsm4(al[na], ad + (SC_QL - SC_QH));
            }
            #pragma unroll
            for (int p = 0; p < 4; p++) {
                uint32_t bd = sb + SC_KH
                    + (wm * 64 + p * 16 + (jm >> 1) * 8 + r8) * SPITCH
                    + ks * 32 + (jm & 1) * 16;
                ldsm4(bh[p], bd);
                ldsm4(bl[p], bd + (SC_KL - SC_KH));
            }
            #pragma unroll
            for (int na = 0; na < 2; na++)
                #pragma unroll
                for (int ma = 0; ma < 8; ma++) {
                    const int p = ma >> 1, s2 = (ma & 1) * 2;
                    mma16816(c[na][ma], ah[na], bh[p][s2], bh[p][s2 + 1]);
                    mma16816(c[na][ma], al[na], bh[p][s2], bh[p][s2 + 1]);
                    mma16816(c[na][ma], ah[na], bl[p][s2], bl[p][s2 + 1]);
                }
        }

        // C -> smem transpose buffer
        #pragma unroll
        for (int na = 0; na < 2; na++)
            #pragma unroll
            for (int ma = 0; ma < 8; ma++) {
                const int rr = wn * 32 + na * 16 + (lane >> 2);
                const int cc = wm * 64 + ma * 8 + (lane & 3) * 2;
                float2 lo = {c[na][ma][0], c[na][ma][1]};
                float2 hi = {c[na][ma][2], c[na][ma][3]};
                *(float2*)&TBf[rr * 132 + cc] = lo;
                *(float2*)&TBf[(rr + 8) * 132 + cc] = hi;
            }
        __syncthreads();

        // coalesced epilogue: warp covers 4 rows x 128B per instr
        float* Eb = E + h * NN;
        #pragma unroll
        for (int i = 0; i < 4; i++) {
            const int r = w * 16 + i * 4 + l8g;
            const int rg = n0g + r;
            float tt = 0.f, tm = 0.f;
            #pragma unroll
            for (int cc = 0; cc < 4; cc++) {
                const int col = cc * 32 + l8 * 4;
                float4 s4 = *(float4*)&TBf[r * 132 + col];
                s4.x *= 0.125f; s4.y *= 0.125f; s4.z *= 0.125f; s4.w *= 0.125f;
                lmin = fminf(lmin, fminf(fminf(s4.x, s4.y), fminf(s4.z, s4.w)));
                float4 e4 = {__expf(s4.x), __expf(s4.y), __expf(s4.z), __expf(s4.w)};
                *(float4*)(Eb + rg * N + m0g + col) = e4;
                float4 nm = mask_not4(mask, rg * N + m0g + col, mo);
                tm += e4.x * nm.x + e4.y * nm.y + e4.z * nm.z + e4.w * nm.w;
                tt += e4.x + e4.y + e4.z + e4.w;
                if (h == 0) {
                    *(float4*)&MBf[r * 132 + col] = s4;
                } else {
                    float4 pm = *(float4*)&MBf[r * 132 + col];
                    pm.x += s4.x; pm.y += s4.y; pm.z += s4.z; pm.w += s4.w;
                    if (h < HH - 1)
                        *(float4*)&MBf[r * 132 + col] = pm;
                    else
                        *(float4*)(meanb + rg * N + m0g + col) = pm;
                }
            }
            tt += __shfl_xor_sync(~0u, tt, 1);
            tt += __shfl_xor_sync(~0u, tt, 2);
            tt += __shfl_xor_sync(~0u, tt, 4);
            tm += __shfl_xor_sync(~0u, tm, 1);
            tm += __shfl_xor_sync(~0u, tm, 2);
            tm += __shfl_xor_sync(~0u, tm, 4);
            if (l8 == 0) {
                g_psu[(h * N + rg) * 16 + blockIdx.x] = tt - tm;
                g_psm[(h * N + rg) * 16 + blockIdx.x] = tm;
            }
        }
        __syncthreads();
    }

    #pragma unroll
    for (int o = 16; o > 0; o >>= 1)
        lmin = fminf(lmin, __shfl_xor_sync(~0u, lmin, o));
    if (lane == 0) red[w] = lmin;
    __syncthreads();
    if (tid == 0) {
        float m = red[0];
        #pragma unroll
        for (int i = 1; i < 8; i++) m = fminf(m, red[i]);
        atomicMin(&g_smin_enc, enc_f(m));
    }
}

// rinv[h][n] = 1 / (sum_unmasked + exp(smin) * sum_masked)
__global__ void rinv_kernel() {
    int idx = blockIdx.x * 256 + threadIdx.x;
    float es = __expf(dec_f(g_smin_enc));
    float a = 0.f, b = 0.f;
    #pragma unroll
    for (int t = 0; t < 16; t++) {
        a += g_psu[idx * 16 + t];
        b += g_psm[idx * 16 + t];
    }
    g_rinv[idx] = 1.0f / (a + es * b);
}

// out2 = mean/8 + smin*notm
__global__ __launch_bounds__(256) void out2_kernel(
    const float* __restrict__ meanb, const void* __restrict__ mask,
    float* __restrict__ out2)
{
    int idx = blockIdx.x * 256 + threadIdx.x;
    const unsigned mo = g_mask_or;
    float smin = dec_f(g_smin_enc);
    out2[idx] = meanb[idx] * 0.125f + smin * mask_not(mask, idx, mo);
}

// -------- PV via mma.sync: 64d x 128n per CTA (one per n-tile,h), K=m ------
#define PV_VH 0
#define PV_VL 9216
#define PV_PH 18432
#define PV_PL 36864
#define PV_TOT 55296

__global__ __launch_bounds__(128) void pv_mma_kernel(
    const float* __restrict__ E, const float* __restrict__ v,
    const void* __restrict__ mask, float* __restrict__ X)
{
    extern __shared__ char dsm[];
    __shared__ float ri[128];
    const int tid = threadIdx.x, lane = tid & 31, w = tid >> 5;
    const int n0 = blockIdx.x * 128, h = blockIdx.y;
    const uint32_t sb = smem_u32(dsm);
    const unsigned mo = g_mask_or;
    const float esm1 = __expf(dec_f(g_smin_enc)) - 1.0f;
    const int r8 = lane & 7, jm = lane >> 3;

    ri[tid] = g_rinv[h * N + tid + n0];
    __syncthreads();

    float c[4][4][4];
    #pragma unroll
    for (int a = 0; a < 4; a++)
        #pragma unroll
        for (int b = 0; b < 4; b++)
            #pragma unroll
            for (int d = 0; d < 4; d++) c[a][b][d] = 0.0f;

    const float* Eb = E + h * NN;
    for (int mc = 0; mc < 32; mc++) {
        const int m0 = mc * 64;
        // stage V: 64 d rows x 64 m, hi/lo
        #pragma unroll
        for (int p = 0; p < 8; p++) {
            const int d = p * 8 + (tid >> 4), m4 = (tid & 15) * 4;
            float4 vv = *(const float4*)(v + (d * HH + h) * N + m0 + m4);
            unsigned h0 = pkbf(vv.x, vv.y), h1 = pkbf(vv.z, vv.w);
            unsigned l0 = pkbf(vv.x - __uint_as_float(h0 << 16),
                               vv.y - __uint_as_float(h0 & 0xFFFF0000u));
            unsigned l1 = pkbf(vv.z - __uint_as_float(h1 << 16),
                               vv.w - __uint_as_float(h1 & 0xFFFF0000u));
            const int off = d * SPITCH + m4 * 2;
            *(unsigned*)(dsm + PV_VH + off) = h0;
            *(unsigned*)(dsm + PV_VH + off + 4) = h1;
            *(unsigned*)(dsm + PV_VL + off) = l0;
            *(unsigned*)(dsm + PV_VL + off + 4) = l1;
        }
        // stage P = E*(1+notm*esm1)*rinv : 128 n rows x 64 m, hi/lo
        #pragma unroll
        for (int p = 0; p < 16; p++) {
            const int n = p * 8 + (tid >> 4), m4 = (tid & 15) * 4;
            float4 e4 = *(const float4*)(Eb + (n0 + n) * N + m0 + m4);
            float4 nm = mask_not4(mask, (n0 + n) * N + m0 + m4, mo);
            float RI = ri[n];
            float4 pv;
            pv.x = e4.x * fmaf(nm.x, esm1, 1.f) * RI;
            pv.y = e4.y * fmaf(nm.y, esm1, 1.f) * RI;
            pv.z = e4.z * fmaf(nm.z, esm1, 1.f) * RI;
            pv.w = e4.w * fmaf(nm.w, esm1, 1.f) * RI;
            unsigned h0 = pkbf(pv.x, pv.y), h1 = pkbf(pv.z, pv.w);
            unsigned l0 = pkbf(pv.x - __uint_as_float(h0 << 16),
                               pv.y - __uint_as_float(h0 & 0xFFFF0000u));
            unsigned l1 = pkbf(pv.z - __uint_as_float(h1 << 16),
                               pv.w - __uint_as_float(h1 & 0xFFFF0000u));
            const int off = n * SPITCH + m4 * 2;
            *(unsigned*)(dsm + PV_PH + off) = h0;
            *(unsigned*)(dsm + PV_PH + off + 4) = h1;
            *(unsigned*)(dsm + PV_PL + off) = l0;
            *(unsigned*)(dsm + PV_PL + off + 4) = l1;
        }
        __syncthreads();

        #pragma unroll
        for (int ks = 0; ks < 4; ks++) {
            unsigned ah[4][4], al[4][4], bh[2][4], bl[2][4];
            #pragma unroll
            for (int da = 0; da < 4; da++) {
                uint32_t ad = sb + PV_VH
                    + (da * 16 + (jm & 1) * 8 + r8) * SPITCH
                    + ks * 32 + (jm >> 1) * 16;
                ldsm4(ah[da], ad);
                ldsm4(al[da], ad + (PV_VL - PV_VH));
            }
            #pragma unroll
            for (int pp = 0; pp < 2; pp++) {
                uint32_t bd = sb + PV_PH
                    + (w * 32 + pp * 16 + (jm >> 1) * 8 + r8) * SPITCH
                    + ks * 32 + (jm & 1) * 16;
                ldsm4(bh[pp], bd);
                ldsm4(bl[pp], bd + (PV_PL - PV_PH));
            }
            #pragma unroll
            for (int da = 0; da < 4; da++)
                #pragma unroll
                for (int pp = 0; pp < 2; pp++)
                    #pragma unroll
                    for (int q = 0; q < 2; q++) {
                        float* cc = c[da][pp * 2 + q];
                        mma16816(cc, ah[da], bh[pp][q * 2], bh[pp][q * 2 + 1]);
                        mma16816(cc, al[da], bh[pp][q * 2], bh[pp][q * 2 + 1]);
                        mma16816(cc, ah[da], bl[pp][q * 2], bl[pp][q * 2 + 1]);
                    }
        }
        __syncthreads();
    }

    // writeback: x[(d*8+h)][n0+n]
    #pragma unroll
    for (int da = 0; da < 4; da++)
        #pragma unroll
        for (int nf = 0; nf < 4; nf++) {
            const int d0 = da * 16 + (lane >> 2);
            const int nc = n0 + w * 32 + nf * 8 + (lane & 3) * 2;
            float2 lo = {c[da][nf][0], c[da][nf][1]};
            float2 hi = {c[da][nf][2], c[da][nf][3]};
            *(float2*)(X + (d0 * HH + h) * N + nc) = lo;
            *(float2*)(X + ((d0 + 8) * HH + h) * N + nc) = hi;
        }
}

// Merge projection: out = Wm @ X + bm
__global__ __launch_bounds__(128) void merge_kernel(
    const float* __restrict__ W, const float* __restrict__ bm,
    const float* __restrict__ X, float* __restrict__ O)
{
    __shared__ float As[2][16][64];
    __shared__ float Bs[2][16][132];
    const int tid = threadIdx.x, tx = tid & 15, ty = tid >> 4;
    const int n0 = blockIdx.x * 128, m0 = blockIdx.y * 64;

    ull acc[8][4];
    #pragma unroll
    for (int i = 0; i < 8; i++)
        #pragma unroll
        for (int j = 0; j < 4; j++) acc[i][j] = 0ull;

    const int ao = tid >> 1, ac = (tid & 1) * 8;
    const float* Ap = W + (m0 + ao) * DM + ac;
    const int brow = tid >> 5, bc4 = tid & 31;
    const float* Bp = X + brow * N + n0 + bc4 * 4;

    float4 ra0, ra1, rb[4];
    ra0 = *(const float4*)(Ap);
    ra1 = *(const float4*)(Ap + 4);
    #pragma unroll
    for (int i = 0; i < 4; i++)
        rb[i] = *(const float4*)(Bp + (i * 4) * N);
    {
        As[0][ac + 0][ao] = ra0.x; As[0][ac + 1][ao] = ra0.y;
        As[0][ac + 2][ao] = ra0.z; As[0][ac + 3][ao] = ra0.w;
        As[0][ac + 4][ao] = ra1.x; As[0][ac + 5][ao] = ra1.y;
        As[0][ac + 6][ao] = ra1.z; As[0][ac + 7][ao] = ra1.w;
        #pragma unroll
        for (int i = 0; i < 4; i++)
            *(float4*)&Bs[0][brow + i * 4][bc4 * 4] = rb[i];
    }
    __syncthreads();

    const int KT = DM / 16;
    for (int kt = 0; kt < KT; kt++) {
        const int s = kt & 1;
        if (kt + 1 < KT) {
            const int c0 = (kt + 1) * 16;
            ra0 = *(const float4*)(Ap + c0);
            ra1 = *(const float4*)(Ap + c0 + 4);
            #pragma unroll
            for (int i = 0; i < 4; i++)
                rb[i] = *(const float4*)(Bp + (c0 + i * 4) * N);
        }
        gemm16(As[s], Bs[s], acc, tx, ty);
        if (kt + 1 < KT) {
            const int d = s ^ 1;
            As[d][ac + 0][ao] = ra0.x; As[d][ac + 1][ao] = ra0.y;
            As[d][ac + 2][ao] = ra0.z; As[d][ac + 3][ao] = ra0.w;
            As[d][ac + 4][ao] = ra1.x; As[d][ac + 5][ao] = ra1.y;
            As[d][ac + 6][ao] = ra1.z; As[d][ac + 7][ao] = ra1.w;
            #pragma unroll
            for (int i = 0; i < 4; i++)
                *(float4*)&Bs[d][brow + i * 4][bc4 * 4] = rb[i];
        }
        __syncthreads();
    }

    #pragma unroll
    for (int i = 0; i < 8; i++) {
        float bias = bm[m0 + ty * 8 + i];
        float2 v0 = up2(acc[i][0]), v1 = up2(acc[i][1]);
        float2 v2 = up2(acc[i][2]), v3 = up2(acc[i][3]);
        float4 o0 = {v0.x + bias, v0.y + bias, v1.x + bias, v1.y + bias};
        float4 o1 = {v2.x + bias, v2.y + bias, v3.x + bias, v3.y + bias};
        float* row = O + (m0 + ty * 8 + i) * N + n0;
        *(float4*)(row + tx * 4) = o0;
        *(float4*)(row + 64 + tx * 4) = o1;
    }
}

// ---------------- launch ----------------
extern "C" void kernel_launch(void* const* d_in, const int* in_sizes, int n_in,
                              void* d_out, int out_size) {
    const float* query = (const float*)d_in[0];
    const float* key   = (const float*)d_in[1];
    const float* value = (const float*)d_in[2];
    const void*  mask  = d_in[4];
    const float* Wq = (const float*)d_in[5];
    const float* bq = (const float*)d_in[6];
    const float* Wk = (const float*)d_in[7];
    const float* bk = (const float*)d_in[8];
    const float* Wv = (const float*)d_in[9];
    const float* bv = (const float*)d_in[10];
    const float* Wm = (const float*)d_in[11];
    const float* bm = (const float*)d_in[12];
    float* out = (float*)d_out;

    float *qp, *kp, *vp, *xp, *Ep, *mp;
    cudaGetSymbolAddress((void**)&qp, g_q);
    cudaGetSymbolAddress((void**)&kp, g_k);
    cudaGetSymbolAddress((void**)&vp, g_v);
    cudaGetSymbolAddress((void**)&xp, g_x);
    cudaGetSymbolAddress((void**)&Ep, g_E);
    cudaGetSymbolAddress((void**)&mp, g_mean);

    cudaFuncSetAttribute(scores_mma_kernel,
                         cudaFuncAttributeMaxDynamicSharedMemorySize, SC_TOT);
    cudaFuncSetAttribute(pv_mma_kernel,
                         cudaFuncAttributeMaxDynamicSharedMemorySize, PV_TOT);

    init_kernel<<<1, 1>>>();
    mask_detect_kernel<<<128, 256>>>((const unsigned*)mask);

    qkv_kernel<<<dim3(N / 128, DM / 64, 3), 128>>>(
        Wq, Wk, Wv, bq, bk, bv, query, key, value, qp, kp, vp);

    scores_mma_kernel<<<dim3(16, 16), 256, SC_TOT>>>(qp, kp, mask, Ep, mp);

    rinv_kernel<<<HH * N / 256, 256>>>();
    out2_kernel<<<NN / 256, 256>>>(mp, mask, out + DM * N);

    pv_mma_kernel<<<dim3(16, HH), 128, PV_TOT>>>(Ep, vp, mask, xp);

    merge_kernel<<<dim3(N / 128, DM / 64), 128>>>(Wm, bm, xp, out);
}

// round 12
// speedup vs baseline: 1.4194x; 1.4194x over previous
#include <cuda_runtime.h>
#include <cstdint>

#define N      2048
#define DM     512
#define HH     8
#define NN     (N * N)

typedef unsigned long long ull;

// ---------------- device scratch ----------------
__device__ float    g_q[DM * N];
__device__ float    g_k[DM * N];
__device__ float    g_v[DM * N];
__device__ float    g_x1[DM * N];
__device__ float    g_x2[DM * N];
__device__ float    g_S[HH * NN];
__device__ float    g_E[HH * NN];
__device__ float    g_psu[HH * N * 16];
__device__ float    g_psm[HH * N * 16];
__device__ float    g_rinv[HH * N];
__device__ unsigned g_smin_enc;
__device__ unsigned g_mask_or;

// ---------------- helpers ----------------
__device__ __forceinline__ unsigned enc_f(float x) {
    unsigned u = __float_as_uint(x);
    return (u & 0x80000000u) ? ~u : (u | 0x80000000u);
}
__device__ __forceinline__ float dec_f(unsigned u) {
    return (u & 0x80000000u) ? __uint_as_float(u & 0x7FFFFFFFu)
                             : __uint_as_float(~u);
}
__device__ __forceinline__ float mask_not(const void* mask, int i, unsigned o) {
    bool mv;
    if (o == 0x3F800000u)      mv = ((const float*)mask)[i] != 0.0f;
    else if (o == 1u)          mv = ((const int*)mask)[i] != 0;
    else                       mv = ((const unsigned char*)mask)[i] != 0;
    return mv ? 0.0f : 1.0f;
}
__device__ __forceinline__ float4 mask_not4(const void* mask, int i, unsigned o) {
    float4 r;
    if (o == 0x3F800000u) {
        float4 m = *(const float4*)((const float*)mask + i);
        r.x = m.x != 0.0f ? 0.f : 1.f; r.y = m.y != 0.0f ? 0.f : 1.f;
        r.z = m.z != 0.0f ? 0.f : 1.f; r.w = m.w != 0.0f ? 0.f : 1.f;
    } else if (o == 1u) {
        int4 m = *(const int4*)((const int*)mask + i);
        r.x = m.x ? 0.f : 1.f; r.y = m.y ? 0.f : 1.f;
        r.z = m.z ? 0.f : 1.f; r.w = m.w ? 0.f : 1.f;
    } else {
        uchar4 m = *(const uchar4*)((const unsigned char*)mask + i);
        r.x = m.x ? 0.f : 1.f; r.y = m.y ? 0.f : 1.f;
        r.z = m.z ? 0.f : 1.f; r.w = m.w ? 0.f : 1.f;
    }
    return r;
}
__device__ __forceinline__ void ffma2(ull& d, ull a, ull b) {
    asm("fma.rn.f32x2 %0, %1, %2, %0;" : "+l"(d) : "l"(a), "l"(b));
}
__device__ __forceinline__ ull pk2(float x, float y) {
    ull r; asm("mov.b64 %0, {%1, %2};" : "=l"(r) : "f"(x), "f"(y)); return r;
}
__device__ __forceinline__ float2 up2(ull p) {
    float2 r; asm("mov.b64 {%0, %1}, %2;" : "=f"(r.x), "=f"(r.y) : "l"(p)); return r;
}
__device__ __forceinline__ uint32_t smem_u32(const void* p) {
    uint32_t a;
    asm("{ .reg .u64 t; cvta.to.shared.u64 t, %1; cvt.u32.u64 %0, t; }"
        : "=r"(a) : "l"(p));
    return a;
}
// pack (a,b) -> bf16x2 with bf16(a) in low half
__device__ __forceinline__ unsigned pkbf(float a, float b) {
    unsigned r; asm("cvt.rn.bf16x2.f32 %0, %1, %2;" : "=r"(r) : "f"(b), "f"(a));
    return r;
}
__device__ __forceinline__ void ldsm4(unsigned* r, uint32_t a) {
    asm volatile("ldmatrix.sync.aligned.m8n8.x4.shared.b16 {%0,%1,%2,%3}, [%4];"
        : "=r"(r[0]), "=r"(r[1]), "=r"(r[2]), "=r"(r[3]) : "r"(a));
}
__device__ __forceinline__ void mma16816(float* c, const unsigned* a,
                                         unsigned b0, unsigned b1) {
    asm volatile(
        "mma.sync.aligned.m16n8k16.row.col.f32.bf16.bf16.f32 "
        "{%0,%1,%2,%3}, {%4,%5,%6,%7}, {%8,%9}, {%0,%1,%2,%3};"
        : "+f"(c[0]), "+f"(c[1]), "+f"(c[2]), "+f"(c[3])
        : "r"(a[0]), "r"(a[1]), "r"(a[2]), "r"(a[3]), "r"(b0), "r"(b1));
}

// ---------------- small kernels ----------------
__global__ void init_kernel() { g_smin_enc = 0xFFFFFFFFu; g_mask_or = 0u; }

__global__ void mask_detect_kernel(const unsigned* __restrict__ m) {
    __shared__ unsigned sh[256];
    unsigned acc = 0;
    const int total = NN / 4;
    for (int i = blockIdx.x * blockDim.x + threadIdx.x; i < total;
         i += gridDim.x * blockDim.x) acc |= m[i];
    sh[threadIdx.x] = acc;
    __syncthreads();
    for (int s = 128; s > 0; s >>= 1) {
        if (threadIdx.x < s) sh[threadIdx.x] |= sh[threadIdx.x + s];
        __syncthreads();
    }
    if (threadIdx.x == 0) atomicOr(&g_mask_or, sh[0]);
}

// ---------------- FFMA2 GEMM core (qkv / merge) ----------------
__device__ __forceinline__ void gemm16(const float (*__restrict__ As)[64],
                                       const float (*__restrict__ Bs)[132],
                                       ull acc[8][4], int tx, int ty) {
    #pragma unroll
    for (int k = 0; k < 16; k++) {
        float4 a0 = *(const float4*)&As[k][ty * 8];
        float4 a1 = *(const float4*)&As[k][ty * 8 + 4];
        float4 b0 = *(const float4*)&Bs[k][tx * 4];
        float4 b1 = *(const float4*)&Bs[k][64 + tx * 4];
        ull pb0 = pk2(b0.x, b0.y), pb1 = pk2(b0.z, b0.w);
        ull pb2 = pk2(b1.x, b1.y), pb3 = pk2(b1.z, b1.w);
        float av[8] = {a0.x, a0.y, a0.z, a0.w, a1.x, a1.y, a1.z, a1.w};
        #pragma unroll
        for (int i = 0; i < 8; i++) {
            ull pa = pk2(av[i], av[i]);
            ffma2(acc[i][0], pa, pb0);
            ffma2(acc[i][1], pa, pb1);
            ffma2(acc[i][2], pa, pb2);
            ffma2(acc[i][3], pa, pb3);
        }
    }
}

__global__ __launch_bounds__(128) void qkv_kernel(
    const float* __restrict__ Wq, const float* __restrict__ Wk,
    const float* __restrict__ Wv, const float* __restrict__ bq,
    const float* __restrict__ bk, const float* __restrict__ bv,
    const float* __restrict__ Xq, const float* __restrict__ Xk,
    const float* __restrict__ Xv,
    float* __restrict__ Oq, float* __restrict__ Ok, float* __restrict__ Ov)
{
    const float *W, *Bv_, *X;
    float* O;
    if (blockIdx.z == 0)      { W = Wq; Bv_ = bq; X = Xq; O = Oq; }
    else if (blockIdx.z == 1) { W = Wk; Bv_ = bk; X = Xk; O = Ok; }
    else                      { W = Wv; Bv_ = bv; X = Xv; O = Ov; }

    __shared__ float As[2][16][64];
    __shared__ float Bs[2][16][132];
    const int tid = threadIdx.x, tx = tid & 15, ty = tid >> 4;
    const int n0 = blockIdx.x * 128, m0 = blockIdx.y * 64;

    ull acc[8][4];
    #pragma unroll
    for (int i = 0; i < 8; i++)
        #pragma unroll
        for (int j = 0; j < 4; j++) acc[i][j] = 0ull;

    const int ao = tid >> 1, ac = (tid & 1) * 8;
    const float* Ap = W + (m0 + ao) * DM + ac;
    const int brow = tid >> 5, bc4 = tid & 31;
    const float* Bp = X + brow * N + n0 + bc4 * 4;

    float4 ra0, ra1, rb[4];
    ra0 = *(const float4*)(Ap);
    ra1 = *(const float4*)(Ap + 4);
    #pragma unroll
    for (int i = 0; i < 4; i++)
        rb[i] = *(const float4*)(Bp + (i * 4) * N);
    {
        As[0][ac + 0][ao] = ra0.x; As[0][ac + 1][ao] = ra0.y;
        As[0][ac + 2][ao] = ra0.z; As[0][ac + 3][ao] = ra0.w;
        As[0][ac + 4][ao] = ra1.x; As[0][ac + 5][ao] = ra1.y;
        As[0][ac + 6][ao] = ra1.z; As[0][ac + 7][ao] = ra1.w;
        #pragma unroll
        for (int i = 0; i < 4; i++)
            *(float4*)&Bs[0][brow + i * 4][bc4 * 4] = rb[i];
    }
    __syncthreads();

    const int KT = DM / 16;
    for (int kt = 0; kt < KT; kt++) {
        const int s = kt & 1;
        if (kt + 1 < KT) {
            const int c0 = (kt + 1) * 16;
            ra0 = *(const float4*)(Ap + c0);
            ra1 = *(const float4*)(Ap + c0 + 4);
            #pragma unroll
            for (int i = 0; i < 4; i++)
                rb[i] = *(const float4*)(Bp + (c0 + i * 4) * N);
        }
        gemm16(As[s], Bs[s], acc, tx, ty);
        if (kt + 1 < KT) {
            const int d = s ^ 1;
            As[d][ac + 0][ao] = ra0.x; As[d][ac + 1][ao] = ra0.y;
            As[d][ac + 2][ao] = ra0.z; As[d][ac + 3][ao] = ra0.w;
            As[d][ac + 4][ao] = ra1.x; As[d][ac + 5][ao] = ra1.y;
            As[d][ac + 6][ao] = ra1.z; As[d][ac + 7][ao] = ra1.w;
            #pragma unroll
            for (int i = 0; i < 4; i++)
                *(float4*)&Bs[d][brow + i * 4][bc4 * 4] = rb[i];
        }
        __syncthreads();
    }

    #pragma unroll
    for (int i = 0; i < 8; i++) {
        float bias = Bv_[m0 + ty * 8 + i];
        float2 v0 = up2(acc[i][0]), v1 = up2(acc[i][1]);
        float2 v2 = up2(acc[i][2]), v3 = up2(acc[i][3]);
        float4 o0 = {v0.x + bias, v0.y + bias, v1.x + bias, v1.y + bias};
        float4 o1 = {v2.x + bias, v2.y + bias, v3.x + bias, v3.y + bias};
        float* row = O + (m0 + ty * 8 + i) * N + n0;
        *(float4*)(row + tx * 4) = o0;
        *(float4*)(row + 64 + tx * 4) = o1;
    }
}

// -------- scores via mma.sync bf16 3-pass: 128n x 128m per CTA, K=64 -------
// staging QH/QL/KH/KL (4 x 18432 = 73728); epilogue reuses it as 128x132 f32.
#define SPITCH 144
#define SM_QH 0
#define SM_QL 18432
#define SM_KH 36864
#define SM_KL 55296
#define SMTOT 73792

__global__ __launch_bounds__(256) void scores_mma_kernel(
    const float* __restrict__ qg, const float* __restrict__ kg,
    const void* __restrict__ mask,
    float* __restrict__ S, float* __restrict__ E)
{
    extern __shared__ char sm[];
    __shared__ float red[8];
    float* TBf = (float*)sm;
    const int tid = threadIdx.x, lane = tid & 31, w = tid >> 5;
    const int wn = w & 3, wm = w >> 2;      // warp tile 32n x 64m
    const int m0g = blockIdx.x * 128, n0g = blockIdx.y * 128;
    const int h = blockIdx.z;
    const uint32_t sb = smem_u32(sm);
    const int r8 = lane & 7, jm = lane >> 3;
    const int l8 = lane & 7, l8g = lane >> 3;

    // stage q,k as bf16 hi/lo, [row][d] pitch 144B
    {
        const int n = tid & 127, dg = tid >> 7;   // 0/1
        #pragma unroll 4
        for (int i = 0; i < 16; i++) {
            const int d = i * 4 + dg * 2;
            float q0 = qg[(d * HH + h) * N + n0g + n];
            float q1 = qg[((d + 1) * HH + h) * N + n0g + n];
            float k0 = kg[(d * HH + h) * N + m0g + n];
            float k1 = kg[((d + 1) * HH + h) * N + m0g + n];
            unsigned qh = pkbf(q0, q1);
            unsigned kh = pkbf(k0, k1);
            unsigned ql = pkbf(q0 - __uint_as_float(qh << 16),
                               q1 - __uint_as_float(qh & 0xFFFF0000u));
            unsigned kl = pkbf(k0 - __uint_as_float(kh << 16),
                               k1 - __uint_as_float(kh & 0xFFFF0000u));
            const int off = n * SPITCH + d * 2;
            *(unsigned*)(sm + SM_QH + off) = qh;
            *(unsigned*)(sm + SM_QL + off) = ql;
            *(unsigned*)(sm + SM_KH + off) = kh;
            *(unsigned*)(sm + SM_KL + off) = kl;
        }
    }
    __syncthreads();

    float c[2][8][4];
    #pragma unroll
    for (int a = 0; a < 2; a++)
        #pragma unroll
        for (int b = 0; b < 8; b++)
            #pragma unroll
            for (int d = 0; d < 4; d++) c[a][b][d] = 0.0f;

    #pragma unroll
    for (int ks = 0; ks < 4; ks++) {
        unsigned ah[2][4], al[2][4], bh[4][4], bl[4][4];
        #pragma unroll
        for (int na = 0; na < 2; na++) {
            uint32_t ad = sb + SM_QH
                + (wn * 32 + na * 16 + (jm & 1) * 8 + r8) * SPITCH
                + ks * 32 + (jm >> 1) * 16;
            ldsm4(ah[na], ad);
            ldsm4(al[na], ad + (SM_QL - SM_QH));
        }
        #pragma unroll
        for (int p = 0; p < 4; p++) {
            uint32_t bd = sb + SM_KH
                + (wm * 64 + p * 16 + (jm >> 1) * 8 + r8) * SPITCH
                + ks * 32 + (jm & 1) * 16;
            ldsm4(bh[p], bd);
            ldsm4(bl[p], bd + (SM_KL - SM_KH));
        }
        #pragma unroll
        for (int na = 0; na < 2; na++)
            #pragma unroll
            for (int ma = 0; ma < 8; ma++) {
                const int p = ma >> 1, s2 = (ma & 1) * 2;
                mma16816(c[na][ma], ah[na], bh[p][s2], bh[p][s2 + 1]);
                mma16816(c[na][ma], al[na], bh[p][s2], bh[p][s2 + 1]);
                mma16816(c[na][ma], ah[na], bl[p][s2], bl[p][s2 + 1]);
            }
    }
    __syncthreads();   // staging fully consumed; reuse as transpose buffer

    // fragments -> smem (fragment-order writes, cheap in smem)
    #pragma unroll
    for (int na = 0; na < 2; na++)
        #pragma unroll
        for (int ma = 0; ma < 8; ma++) {
            const int rr = wn * 32 + na * 16 + (lane >> 2);
            const int cc = wm * 64 + ma * 8 + (lane & 3) * 2;
            float2 lo = {c[na][ma][0], c[na][ma][1]};
            float2 hi = {c[na][ma][2], c[na][ma][3]};
            *(float2*)&TBf[rr * 132 + cc] = lo;
            *(float2*)&TBf[(rr + 8) * 132 + cc] = hi;
        }
    __syncthreads();

    // coalesced epilogue: warp = 4 rows x 128B per access
    const unsigned mo = g_mask_or;
    float lmin = 3.0e38f;
    float* Sb = S + h * NN;
    float* Eb = E + h * NN;
    #pragma unroll
    for (int i = 0; i < 4; i++) {
        const int r = w * 16 + i * 4 + l8g;
        const int rg = n0g + r;
        float tt = 0.f, tm = 0.f;
        #pragma unroll
        for (int cc = 0; cc < 4; cc++) {
            const int col = cc * 32 + l8 * 4;
            float4 s4 = *(float4*)&TBf[r * 132 + col];
            s4.x *= 0.125f; s4.y *= 0.125f; s4.z *= 0.125f; s4.w *= 0.125f;
            lmin = fminf(lmin, fminf(fminf(s4.x, s4.y), fminf(s4.z, s4.w)));
            *(float4*)(Sb + rg * N + m0g + col) = s4;
            float4 e4 = {__expf(s4.x), __expf(s4.y), __expf(s4.z), __expf(s4.w)};
            *(float4*)(Eb + rg * N + m0g + col) = e4;
            float4 nm = mask_not4(mask, rg * N + m0g + col, mo);
            tm += e4.x * nm.x + e4.y * nm.y + e4.z * nm.z + e4.w * nm.w;
            tt += e4.x + e4.y + e4.z + e4.w;
        }
        tt += __shfl_xor_sync(~0u, tt, 1);
        tt += __shfl_xor_sync(~0u, tt, 2);
        tt += __shfl_xor_sync(~0u, tt, 4);
        tm += __shfl_xor_sync(~0u, tm, 1);
        tm += __shfl_xor_sync(~0u, tm, 2);
        tm += __shfl_xor_sync(~0u, tm, 4);
        if (l8 == 0) {
            g_psu[(h * N + rg) * 16 + blockIdx.x] = tt - tm;
            g_psm[(h * N + rg) * 16 + blockIdx.x] = tm;
        }
    }
    #pragma unroll
    for (int o = 16; o > 0; o >>= 1)
        lmin = fminf(lmin, __shfl_xor_sync(~0u, lmin, o));
    if (lane == 0) red[w] = lmin;
    __syncthreads();
    if (tid == 0) {
        float m = red[0];
        #pragma unroll
        for (int i = 1; i < 8; i++) m = fminf(m, red[i]);
        atomicMin(&g_smin_enc, enc_f(m));
    }
}

// rinv[h][n] = 1 / (sum_unmasked + exp(smin) * sum_masked)
__global__ void rinv_kernel() {
    int idx = blockIdx.x * 256 + threadIdx.x;
    float es = __expf(dec_f(g_smin_enc));
    float a = 0.f, b = 0.f;
    #pragma unroll
    for (int t = 0; t < 16; t++) {
        a += g_psu[idx * 16 + t];
        b += g_psm[idx * 16 + t];
    }
    g_rinv[idx] = 1.0f / (a + es * b);
}

__global__ __launch_bounds__(256) void mean_kernel(
    const float* __restrict__ S, const void* __restrict__ mask,
    float* __restrict__ out2)
{
    int idx = blockIdx.x * 256 + threadIdx.x;
    const unsigned mo = g_mask_or;
    float smin = dec_f(g_smin_enc);
    float s = 0.0f;
    #pragma unroll
    for (int h = 0; h < HH; h++) s += S[h * NN + idx];
    out2[idx] = s * 0.125f + smin * mask_not(mask, idx, mo);
}

// -------- PV via mma.sync: 64d x 128n per CTA, m-half split, K=m ----------
#define PV_VH 0
#define PV_VL 9216
#define PV_PH 18432
#define PV_PL 36864
#define PV_TOT 55296

__global__ __launch_bounds__(128) void pv_mma_kernel(
    const float* __restrict__ E, const float* __restrict__ v,
    const void* __restrict__ mask,
    float* __restrict__ X1, float* __restrict__ X2)
{
    extern __shared__ char dsm[];
    __shared__ float ri[128];
    const int tid = threadIdx.x, lane = tid & 31, w = tid >> 5;
    const int n0 = blockIdx.x * 128, h = blockIdx.z;
    const int mbase = blockIdx.y * (N / 2);
    float* X = blockIdx.y ? X2 : X1;
    const uint32_t sb = smem_u32(dsm);
    const unsigned mo = g_mask_or;
    const float esm1 = __expf(dec_f(g_smin_enc)) - 1.0f;
    const int r8 = lane & 7, jm = lane >> 3;

    ri[tid] = g_rinv[h * N + tid + n0];
    __syncthreads();

    float c[4][4][4];
    #pragma unroll
    for (int a = 0; a < 4; a++)
        #pragma unroll
        for (int b = 0; b < 4; b++)
            #pragma unroll
            for (int d = 0; d < 4; d++) c[a][b][d] = 0.0f;

    const float* Eb = E + h * NN;
    for (int mc = 0; mc < 16; mc++) {
        const int m0 = mbase + mc * 64;
        // stage V: 64 d rows x 64 m, hi/lo
        #pragma unroll
        for (int p = 0; p < 8; p++) {
            const int d = p * 8 + (tid >> 4), m4 = (tid & 15) * 4;
            float4 vv = *(const float4*)(v + (d * HH + h) * N + m0 + m4);
            unsigned h0 = pkbf(vv.x, vv.y), h1 = pkbf(vv.z, vv.w);
            unsigned l0 = pkbf(vv.x - __uint_as_float(h0 << 16),
                               vv.y - __uint_as_float(h0 & 0xFFFF0000u));
            unsigned l1 = pkbf(vv.z - __uint_as_float(h1 << 16),
                               vv.w - __uint_as_float(h1 & 0xFFFF0000u));
            const int off = d * SPITCH + m4 * 2;
            *(unsigned*)(dsm + PV_VH + off) = h0;
            *(unsigned*)(dsm + PV_VH + off + 4) = h1;
            *(unsigned*)(dsm + PV_VL + off) = l0;
            *(unsigned*)(dsm + PV_VL + off + 4) = l1;
        }
        // stage P = E*(1+notm*esm1)*rinv : 128 n rows x 64 m, hi/lo
        #pragma unroll
        for (int p = 0; p < 16; p++) {
            const int n = p * 8 + (tid >> 4), m4 = (tid & 15) * 4;
            float4 e4 = *(const float4*)(Eb + (n0 + n) * N + m0 + m4);
            float4 nm = mask_not4(mask, (n0 + n) * N + m0 + m4, mo);
            float RI = ri[n];
            float4 pv;
            pv.x = e4.x * fmaf(nm.x, esm1, 1.f) * RI;
            pv.y = e4.y * fmaf(nm.y, esm1, 1.f) * RI;
            pv.z = e4.z * fmaf(nm.z, esm1, 1.f) * RI;
            pv.w = e4.w * fmaf(nm.w, esm1, 1.f) * RI;
            unsigned h0 = pkbf(pv.x, pv.y), h1 = pkbf(pv.z, pv.w);
            unsigned l0 = pkbf(pv.x - __uint_as_float(h0 << 16),
                               pv.y - __uint_as_float(h0 & 0xFFFF0000u));
            unsigned l1 = pkbf(pv.z - __uint_as_float(h1 << 16),
                               pv.w - __uint_as_float(h1 & 0xFFFF0000u));
            const int off = n * SPITCH + m4 * 2;
            *(unsigned*)(dsm + PV_PH + off) = h0;
            *(unsigned*)(dsm + PV_PH + off + 4) = h1;
            *(unsigned*)(dsm + PV_PL + off) = l0;
            *(unsigned*)(dsm + PV_PL + off + 4) = l1;
        }
        __syncthreads();

        #pragma unroll
        for (int ks = 0; ks < 4; ks++) {
            unsigned ah[4][4], al[4][4], bh[2][4], bl[2][4];
            #pragma unroll
            for (int da = 0; da < 4; da++) {
                uint32_t ad = sb + PV_VH
                    + (da * 16 + (jm & 1) * 8 + r8) * SPITCH
                    + ks * 32 + (jm >> 1) * 16;
                ldsm4(ah[da], ad);
                ldsm4(al[da], ad + (PV_VL - PV_VH));
            }
            #pragma unroll
            for (int pp = 0; pp < 2; pp++) {
                uint32_t bd = sb + PV_PH
                    + (w * 32 + pp * 16 + (jm >> 1) * 8 + r8) * SPITCH
                    + ks * 32 + (jm & 1) * 16;
                ldsm4(bh[pp], bd);
                ldsm4(bl[pp], bd + (PV_PL - PV_PH));
            }
            #pragma unroll
            for (int da = 0; da < 4; da++)
                #pragma unroll
                for (int pp = 0; pp < 2; pp++)
                    #pragma unroll
                    for (int q = 0; q < 2; q++) {
                        float* cc = c[da][pp * 2 + q];
                        mma16816(cc, ah[da], bh[pp][q * 2], bh[pp][q * 2 + 1]);
                        mma16816(cc, al[da], bh[pp][q * 2], bh[pp][q * 2 + 1]);
                        mma16816(cc, ah[da], bl[pp][q * 2], bl[pp][q * 2 + 1]);
                    }
        }
        __syncthreads();
    }

    // writeback: x[(d*8+h)][n0+n]
    #pragma unroll
    for (int da = 0; da < 4; da++)
        #pragma unroll
        for (int nf = 0; nf < 4; nf++) {
            const int d0 = da * 16 + (lane >> 2);
            const int nc = n0 + w * 32 + nf * 8 + (lane & 3) * 2;
            float2 lo = {c[da][nf][0], c[da][nf][1]};
            float2 hi = {c[da][nf][2], c[da][nf][3]};
            *(float2*)(X + (d0 * HH + h) * N + nc) = lo;
            *(float2*)(X + ((d0 + 8) * HH + h) * N + nc) = hi;
        }
}

// Merge projection: out = Wm @ (x1 + x2) + bm
__global__ __launch_bounds__(128) void merge_kernel(
    const float* __restrict__ W, const float* __restrict__ bm,
    const float* __restrict__ X1, const float* __restrict__ X2,
    float* __restrict__ O)
{
    __shared__ float As[2][16][64];
    __shared__ float Bs[2][16][132];
    const int tid = threadIdx.x, tx = tid & 15, ty = tid >> 4;
    const int n0 = blockIdx.x * 128, m0 = blockIdx.y * 64;

    ull acc[8][4];
    #pragma unroll
    for (int i = 0; i < 8; i++)
        #pragma unroll
        for (int j = 0; j < 4; j++) acc[i][j] = 0ull;

    const int ao = tid >> 1, ac = (tid & 1) * 8;
    const float* Ap = W + (m0 + ao) * DM + ac;
    const int brow = tid >> 5, bc4 = tid & 31;
    const float* B1 = X1 + brow * N + n0 + bc4 * 4;
    const float* B2 = X2 + brow * N + n0 + bc4 * 4;

    float4 ra0, ra1, rb[4];
    ra0 = *(const float4*)(Ap);
    ra1 = *(const float4*)(Ap + 4);
    #pragma unroll
    for (int i = 0; i < 4; i++) {
        float4 a = *(const float4*)(B1 + (i * 4) * N);
        float4 b = *(const float4*)(B2 + (i * 4) * N);
        rb[i] = make_float4(a.x + b.x, a.y + b.y, a.z + b.z, a.w + b.w);
    }
    {
        As[0][ac + 0][ao] = ra0.x; As[0][ac + 1][ao] = ra0.y;
        As[0][ac + 2][ao] = ra0.z; As[0][ac + 3][ao] = ra0.w;
        As[0][ac + 4][ao] = ra1.x; As[0][ac + 5][ao] = ra1.y;
        As[0][ac + 6][ao] = ra1.z; As[0][ac + 7][ao] = ra1.w;
        #pragma unroll
        for (int i = 0; i < 4; i++)
            *(float4*)&Bs[0][brow + i * 4][bc4 * 4] = rb[i];
    }
    __syncthreads();

    const int KT = DM / 16;
    for (int kt = 0; kt < KT; kt++) {
        const int s = kt & 1;
        if (kt + 1 < KT) {
            const int c0 = (kt + 1) * 16;
            ra0 = *(const float4*)(Ap + c0);
            ra1 = *(const float4*)(Ap + c0 + 4);
            #pragma unroll
            for (int i = 0; i < 4; i++) {
                float4 a = *(const float4*)(B1 + (c0 + i * 4) * N);
                float4 b = *(const float4*)(B2 + (c0 + i * 4) * N);
                rb[i] = make_float4(a.x + b.x, a.y + b.y, a.z + b.z, a.w + b.w);
            }
        }
        gemm16(As[s], Bs[s], acc, tx, ty);
        if (kt + 1 < KT) {
            const int d = s ^ 1;
            As[d][ac + 0][ao] = ra0.x; As[d][ac + 1][ao] = ra0.y;
            As[d][ac + 2][ao] = ra0.z; As[d][ac + 3][ao] = ra0.w;
            As[d][ac + 4][ao] = ra1.x; As[d][ac + 5][ao] = ra1.y;
            As[d][ac + 6][ao] = ra1.z; As[d][ac + 7][ao] = ra1.w;
            #pragma unroll
            for (int i = 0; i < 4; i++)
                *(float4*)&Bs[d][brow + i * 4][bc4 * 4] = rb[i];
        }
        __syncthreads();
    }

    #pragma unroll
    for (int i = 0; i < 8; i++) {
        float bias = bm[m0 + ty * 8 + i];
        float2 v0 = up2(acc[i][0]), v1 = up2(acc[i][1]);
        float2 v2 = up2(acc[i][2]), v3 = up2(acc[i][3]);
        float4 o0 = {v0.x + bias, v0.y + bias, v1.x + bias, v1.y + bias};
        float4 o1 = {v2.x + bias, v2.y + bias, v3.x + bias, v3.y + bias};
        float* row = O + (m0 + ty * 8 + i) * N + n0;
        *(float4*)(row + tx * 4) = o0;
        *(float4*)(row + 64 + tx * 4) = o1;
    }
}

// ---------------- launch ----------------
extern "C" void kernel_launch(void* const* d_in, const int* in_sizes, int n_in,
                              void* d_out, int out_size) {
    const float* query = (const float*)d_in[0];
    const float* key   = (const float*)d_in[1];
    const float* value = (const float*)d_in[2];
    const void*  mask  = d_in[4];
    const float* Wq = (const float*)d_in[5];
    const float* bq = (const float*)d_in[6];
    const float* Wk = (const float*)d_in[7];
    const float* bk = (const float*)d_in[8];
    const float* Wv = (const float*)d_in[9];
    const float* bv = (const float*)d_in[10];
    const float* Wm = (const float*)d_in[11];
    const float* bm = (const float*)d_in[12];
    float* out = (float*)d_out;

    float *qp, *kp, *vp, *x1p, *x2p, *Sp, *Ep;
    cudaGetSymbolAddress((void**)&qp, g_q);
    cudaGetSymbolAddress((void**)&kp, g_k);
    cudaGetSymbolAddress((void**)&vp, g_v);
    cudaGetSymbolAddress((void**)&x1p, g_x1);
    cudaGetSymbolAddress((void**)&x2p, g_x2);
    cudaGetSymbolAddress((void**)&Sp, g_S);
    cudaGetSymbolAddress((void**)&Ep, g_E);

    cudaFuncSetAttribute(scores_mma_kernel,
                         cudaFuncAttributeMaxDynamicSharedMemorySize, SMTOT);
    cudaFuncSetAttribute(pv_mma_kernel,
                         cudaFuncAttributeMaxDynamicSharedMemorySize, PV_TOT);

    init_kernel<<<1, 1>>>();
    mask_detect_kernel<<<128, 256>>>((const unsigned*)mask);

    qkv_kernel<<<dim3(N / 128, DM / 64, 3), 128>>>(
        Wq, Wk, Wv, bq, bk, bv, query, key, value, qp, kp, vp);

    scores_mma_kernel<<<dim3(16, 16, HH), 256, SMTOT>>>(qp, kp, mask, Sp, Ep);

    rinv_kernel<<<HH * N / 256, 256>>>();
    mean_kernel<<<NN / 256, 256>>>(Sp, mask, out + DM * N);

    pv_mma_kernel<<<dim3(16, 2, HH), 128, PV_TOT>>>(Ep, vp, mask, x1p, x2p);

    merge_kernel<<<dim3(N / 128, DM / 64), 128>>>(Wm, bm, x1p, x2p, out);
}

// round 13
// speedup vs baseline: 1.6736x; 1.1791x over previous
#include <cuda_runtime.h>
#include <cstdint>

#define N      2048
#define DM     512
#define HH     8
#define NN     (N * N)

typedef unsigned long long ull;

// ---------------- device scratch ----------------
__device__ float    g_q[DM * N];
__device__ float    g_k[DM * N];
__device__ float    g_v[DM * N];
__device__ float    g_x1[DM * N];
__device__ float    g_x2[DM * N];
__device__ float    g_S[HH * NN];
__device__ float    g_E[HH * NN];
__device__ float    g_psu[HH * N * 16];
__device__ float    g_psm[HH * N * 16];
__device__ float    g_rinv[HH * N];
__device__ unsigned g_smin_enc;
__device__ unsigned g_mask_or;

// ---------------- helpers ----------------
__device__ __forceinline__ unsigned enc_f(float x) {
    unsigned u = __float_as_uint(x);
    return (u & 0x80000000u) ? ~u : (u | 0x80000000u);
}
__device__ __forceinline__ float dec_f(unsigned u) {
    return (u & 0x80000000u) ? __uint_as_float(u & 0x7FFFFFFFu)
                             : __uint_as_float(~u);
}
__device__ __forceinline__ float mask_not(const void* mask, int i, unsigned o) {
    bool mv;
    if (o == 0x3F800000u)      mv = ((const float*)mask)[i] != 0.0f;
    else if (o == 1u)          mv = ((const int*)mask)[i] != 0;
    else                       mv = ((const unsigned char*)mask)[i] != 0;
    return mv ? 0.0f : 1.0f;
}
__device__ __forceinline__ float4 mask_not4(const void* mask, int i, unsigned o) {
    float4 r;
    if (o == 0x3F800000u) {
        float4 m = *(const float4*)((const float*)mask + i);
        r.x = m.x != 0.0f ? 0.f : 1.f; r.y = m.y != 0.0f ? 0.f : 1.f;
        r.z = m.z != 0.0f ? 0.f : 1.f; r.w = m.w != 0.0f ? 0.f : 1.f;
    } else if (o == 1u) {
        int4 m = *(const int4*)((const int*)mask + i);
        r.x = m.x ? 0.f : 1.f; r.y = m.y ? 0.f : 1.f;
        r.z = m.z ? 0.f : 1.f; r.w = m.w ? 0.f : 1.f;
    } else {
        uchar4 m = *(const uchar4*)((const unsigned char*)mask + i);
        r.x = m.x ? 0.f : 1.f; r.y = m.y ? 0.f : 1.f;
        r.z = m.z ? 0.f : 1.f; r.w = m.w ? 0.f : 1.f;
    }
    return r;
}
__device__ __forceinline__ void ffma2(ull& d, ull a, ull b) {
    asm("fma.rn.f32x2 %0, %1, %2, %0;" : "+l"(d) : "l"(a), "l"(b));
}
__device__ __forceinline__ ull pk2(float x, float y) {
    ull r; asm("mov.b64 %0, {%1, %2};" : "=l"(r) : "f"(x), "f"(y)); return r;
}
__device__ __forceinline__ float2 up2(ull p) {
    float2 r; asm("mov.b64 {%0, %1}, %2;" : "=f"(r.x), "=f"(r.y) : "l"(p)); return r;
}
__device__ __forceinline__ uint32_t smem_u32(const void* p) {
    uint32_t a;
    asm("{ .reg .u64 t; cvta.to.shared.u64 t, %1; cvt.u32.u64 %0, t; }"
        : "=r"(a) : "l"(p));
    return a;
}
// pack (a,b) -> bf16x2 with bf16(a) in low half
__device__ __forceinline__ unsigned pkbf(float a, float b) {
    unsigned r; asm("cvt.rn.bf16x2.f32 %0, %1, %2;" : "=r"(r) : "f"(b), "f"(a));
    return r;
}
__device__ __forceinline__ void ldsm4(unsigned* r, uint32_t a) {
    asm volatile("ldmatrix.sync.aligned.m8n8.x4.shared.b16 {%0,%1,%2,%3}, [%4];"
        : "=r"(r[0]), "=r"(r[1]), "=r"(r[2]), "=r"(r[3]) : "r"(a));
}
__device__ __forceinline__ void mma16816(float* c, const unsigned* a,
                                         unsigned b0, unsigned b1) {
    asm volatile(
        "mma.sync.aligned.m16n8k16.row.col.f32.bf16.bf16.f32 "
        "{%0,%1,%2,%3}, {%4,%5,%6,%7}, {%8,%9}, {%0,%1,%2,%3};"
        : "+f"(c[0]), "+f"(c[1]), "+f"(c[2]), "+f"(c[3])
        : "r"(a[0]), "r"(a[1]), "r"(a[2]), "r"(a[3]), "r"(b0), "r"(b1));
}

// ---------------- small kernels ----------------
__global__ void init_kernel() { g_smin_enc = 0xFFFFFFFFu; g_mask_or = 0u; }

__global__ void mask_detect_kernel(const unsigned* __restrict__ m) {
    __shared__ unsigned sh[256];
    unsigned acc = 0;
    const int total = NN / 4;
    for (int i = blockIdx.x * blockDim.x + threadIdx.x; i < total;
         i += gridDim.x * blockDim.x) acc |= m[i];
    sh[threadIdx.x] = acc;
    __syncthreads();
    for (int s = 128; s > 0; s >>= 1) {
        if (threadIdx.x < s) sh[threadIdx.x] |= sh[threadIdx.x + s];
        __syncthreads();
    }
    if (threadIdx.x == 0) atomicOr(&g_mask_or, sh[0]);
}

// ---------------- FFMA2 GEMM core (qkv / pv / merge) ----------------
__device__ __forceinline__ void gemm16(const float (*__restrict__ As)[64],
                                       const float (*__restrict__ Bs)[132],
                                       ull acc[8][4], int tx, int ty) {
    #pragma unroll
    for (int k = 0; k < 16; k++) {
        float4 a0 = *(const float4*)&As[k][ty * 8];
        float4 a1 = *(const float4*)&As[k][ty * 8 + 4];
        float4 b0 = *(const float4*)&Bs[k][tx * 4];
        float4 b1 = *(const float4*)&Bs[k][64 + tx * 4];
        ull pb0 = pk2(b0.x, b0.y), pb1 = pk2(b0.z, b0.w);
        ull pb2 = pk2(b1.x, b1.y), pb3 = pk2(b1.z, b1.w);
        float av[8] = {a0.x, a0.y, a0.z, a0.w, a1.x, a1.y, a1.z, a1.w};
        #pragma unroll
        for (int i = 0; i < 8; i++) {
            ull pa = pk2(av[i], av[i]);
            ffma2(acc[i][0], pa, pb0);
            ffma2(acc[i][1], pa, pb1);
            ffma2(acc[i][2], pa, pb2);
            ffma2(acc[i][3], pa, pb3);
        }
    }
}

__global__ __launch_bounds__(128) void qkv_kernel(
    const float* __restrict__ Wq, const float* __restrict__ Wk,
    const float* __restrict__ Wv, const float* __restrict__ bq,
    const float* __restrict__ bk, const float* __restrict__ bv,
    const float* __restrict__ Xq, const float* __restrict__ Xk,
    const float* __restrict__ Xv,
    float* __restrict__ Oq, float* __restrict__ Ok, float* __restrict__ Ov)
{
    const float *W, *Bv_, *X;
    float* O;
    if (blockIdx.z == 0)      { W = Wq; Bv_ = bq; X = Xq; O = Oq; }
    else if (blockIdx.z == 1) { W = Wk; Bv_ = bk; X = Xk; O = Ok; }
    else                      { W = Wv; Bv_ = bv; X = Xv; O = Ov; }

    __shared__ float As[2][16][64];
    __shared__ float Bs[2][16][132];
    const int tid = threadIdx.x, tx = tid & 15, ty = tid >> 4;
    const int n0 = blockIdx.x * 128, m0 = blockIdx.y * 64;

    ull acc[8][4];
    #pragma unroll
    for (int i = 0; i < 8; i++)
        #pragma unroll
        for (int j = 0; j < 4; j++) acc[i][j] = 0ull;

    const int ao = tid >> 1, ac = (tid & 1) * 8;
    const float* Ap = W + (m0 + ao) * DM + ac;
    const int brow = tid >> 5, bc4 = tid & 31;
    const float* Bp = X + brow * N + n0 + bc4 * 4;

    float4 ra0, ra1, rb[4];
    ra0 = *(const float4*)(Ap);
    ra1 = *(const float4*)(Ap + 4);
    #pragma unroll
    for (int i = 0; i < 4; i++)
        rb[i] = *(const float4*)(Bp + (i * 4) * N);
    {
        As[0][ac + 0][ao] = ra0.x; As[0][ac + 1][ao] = ra0.y;
        As[0][ac + 2][ao] = ra0.z; As[0][ac + 3][ao] = ra0.w;
        As[0][ac + 4][ao] = ra1.x; As[0][ac + 5][ao] = ra1.y;
        As[0][ac + 6][ao] = ra1.z; As[0][ac + 7][ao] = ra1.w;
        #pragma unroll
        for (int i = 0; i < 4; i++)
            *(float4*)&Bs[0][brow + i * 4][bc4 * 4] = rb[i];
    }
    __syncthreads();

    const int KT = DM / 16;
    for (int kt = 0; kt < KT; kt++) {
        const int s = kt & 1;
        if (kt + 1 < KT) {
            const int c0 = (kt + 1) * 16;
            ra0 = *(const float4*)(Ap + c0);
            ra1 = *(const float4*)(Ap + c0 + 4);
            #pragma unroll
            for (int i = 0; i < 4; i++)
                rb[i] = *(const float4*)(Bp + (c0 + i * 4) * N);
        }
        gemm16(As[s], Bs[s], acc, tx, ty);
        if (kt + 1 < KT) {
            const int d = s ^ 1;
            As[d][ac + 0][ao] = ra0.x; As[d][ac + 1][ao] = ra0.y;
            As[d][ac + 2][ao] = ra0.z; As[d][ac + 3][ao] = ra0.w;
            As[d][ac + 4][ao] = ra1.x; As[d][ac + 5][ao] = ra1.y;
            As[d][ac + 6][ao] = ra1.z; As[d][ac + 7][ao] = ra1.w;
            #pragma unroll
            for (int i = 0; i < 4; i++)
                *(float4*)&Bs[d][brow + i * 4][bc4 * 4] = rb[i];
        }
        __syncthreads();
    }

    #pragma unroll
    for (int i = 0; i < 8; i++) {
        float bias = Bv_[m0 + ty * 8 + i];
        float2 v0 = up2(acc[i][0]), v1 = up2(acc[i][1]);
        float2 v2 = up2(acc[i][2]), v3 = up2(acc[i][3]);
        float4 o0 = {v0.x + bias, v0.y + bias, v1.x + bias, v1.y + bias};
        float4 o1 = {v2.x + bias, v2.y + bias, v3.x + bias, v3.y + bias};
        float* row = O + (m0 + ty * 8 + i) * N + n0;
        *(float4*)(row + tx * 4) = o0;
        *(float4*)(row + 64 + tx * 4) = o1;
    }
}

// -------- scores via mma.sync bf16 3-pass: 128n x 128m per CTA, K=64 -------
// staging QH/QL/KH/KL (4 x 18432 = 73728); epilogue reuses it as 128x132 f32.
#define SPITCH 144
#define SM_QH 0
#define SM_QL 18432
#define SM_KH 36864
#define SM_KL 55296
#define SMTOT 73792

__global__ __launch_bounds__(256) void scores_mma_kernel(
    const float* __restrict__ qg, const float* __restrict__ kg,
    const void* __restrict__ mask,
    float* __restrict__ S, float* __restrict__ E)
{
    extern __shared__ char sm[];
    __shared__ float red[8];
    float* TBf = (float*)sm;
    const int tid = threadIdx.x, lane = tid & 31, w = tid >> 5;
    const int wn = w & 3, wm = w >> 2;      // warp tile 32n x 64m
    const int m0g = blockIdx.x * 128, n0g = blockIdx.y * 128;
    const int h = blockIdx.z;
    const uint32_t sb = smem_u32(sm);
    const int r8 = lane & 7, jm = lane >> 3;
    const int l8 = lane & 7, l8g = lane >> 3;

    // stage q,k as bf16 hi/lo, [row][d] pitch 144B
    {
        const int n = tid & 127, dg = tid >> 7;   // 0/1
        #pragma unroll 4
        for (int i = 0; i < 16; i++) {
            const int d = i * 4 + dg * 2;
            float q0 = qg[(d * HH + h) * N + n0g + n];
            float q1 = qg[((d + 1) * HH + h) * N + n0g + n];
            float k0 = kg[(d * HH + h) * N + m0g + n];
            float k1 = kg[((d + 1) * HH + h) * N + m0g + n];
            unsigned qh = pkbf(q0, q1);
            unsigned kh = pkbf(k0, k1);
            unsigned ql = pkbf(q0 - __uint_as_float(qh << 16),
                               q1 - __uint_as_float(qh & 0xFFFF0000u));
            unsigned kl = pkbf(k0 - __uint_as_float(kh << 16),
                               k1 - __uint_as_float(kh & 0xFFFF0000u));
            const int off = n * SPITCH + d * 2;
            *(unsigned*)(sm + SM_QH + off) = qh;
            *(unsigned*)(sm + SM_QL + off) = ql;
            *(unsigned*)(sm + SM_KH + off) = kh;
            *(unsigned*)(sm + SM_KL + off) = kl;
        }
    }
    __syncthreads();

    float c[2][8][4];
    #pragma unroll
    for (int a = 0; a < 2; a++)
        #pragma unroll
        for (int b = 0; b < 8; b++)
            #pragma unroll
            for (int d = 0; d < 4; d++) c[a][b][d] = 0.0f;

    #pragma unroll
    for (int ks = 0; ks < 4; ks++) {
        unsigned ah[2][4], al[2][4], bh[4][4], bl[4][4];
        #pragma unroll
        for (int na = 0; na < 2; na++) {
            uint32_t ad = sb + SM_QH
                + (wn * 32 + na * 16 + (jm & 1) * 8 + r8) * SPITCH
                + ks * 32 + (jm >> 1) * 16;
            ldsm4(ah[na], ad);
            ldsm4(al[na], ad + (SM_QL - SM_QH));
        }
        #pragma unroll
        for (int p = 0; p < 4; p++) {
            uint32_t bd = sb + SM_KH
                + (wm * 64 + p * 16 + (jm >> 1) * 8 + r8) * SPITCH
                + ks * 32 + (jm & 1) * 16;
            ldsm4(bh[p], bd);
            ldsm4(bl[p], bd + (SM_KL - SM_KH));
        }
        #pragma unroll
        for (int na = 0; na < 2; na++)
            #pragma unroll
            for (int ma = 0; ma < 8; ma++) {
                const int p = ma >> 1, s2 = (ma & 1) * 2;
                mma16816(c[na][ma], ah[na], bh[p][s2], bh[p][s2 + 1]);
                mma16816(c[na][ma], al[na], bh[p][s2], bh[p][s2 + 1]);
                mma16816(c[na][ma], ah[na], bl[p][s2], bl[p][s2 + 1]);
            }
    }
    __syncthreads();   // staging fully consumed; reuse as transpose buffer

    // fragments -> smem (fragment-order writes, cheap in smem)
    #pragma unroll
    for (int na = 0; na < 2; na++)
        #pragma unroll
        for (int ma = 0; ma < 8; ma++) {
            const int rr = wn * 32 + na * 16 + (lane >> 2);
            const int cc = wm * 64 + ma * 8 + (lane & 3) * 2;
            float2 lo = {c[na][ma][0], c[na][ma][1]};
            float2 hi = {c[na][ma][2], c[na][ma][3]};
            *(float2*)&TBf[rr * 132 + cc] = lo;
            *(float2*)&TBf[(rr + 8) * 132 + cc] = hi;
        }
    __syncthreads();

    // coalesced epilogue: warp = 4 rows x 128B per access
    const unsigned mo = g_mask_or;
    float lmin = 3.0e38f;
    float* Sb = S + h * NN;
    float* Eb = E + h * NN;
    #pragma unroll
    for (int i = 0; i < 4; i++) {
        const int r = w * 16 + i * 4 + l8g;
        const int rg = n0g + r;
        float tt = 0.f, tm = 0.f;
        #pragma unroll
        for (int cc = 0; cc < 4; cc++) {
            const int col = cc * 32 + l8 * 4;
            float4 s4 = *(float4*)&TBf[r * 132 + col];
            s4.x *= 0.125f; s4.y *= 0.125f; s4.z *= 0.125f; s4.w *= 0.125f;
            lmin = fminf(lmin, fminf(fminf(s4.x, s4.y), fminf(s4.z, s4.w)));
            *(float4*)(Sb + rg * N + m0g + col) = s4;
            float4 e4 = {__expf(s4.x), __expf(s4.y), __expf(s4.z), __expf(s4.w)};
            *(float4*)(Eb + rg * N + m0g + col) = e4;
            float4 nm = mask_not4(mask, rg * N + m0g + col, mo);
            tm += e4.x * nm.x + e4.y * nm.y + e4.z * nm.z + e4.w * nm.w;
            tt += e4.x + e4.y + e4.z + e4.w;
        }
        tt += __shfl_xor_sync(~0u, tt, 1);
        tt += __shfl_xor_sync(~0u, tt, 2);
        tt += __shfl_xor_sync(~0u, tt, 4);
        tm += __shfl_xor_sync(~0u, tm, 1);
        tm += __shfl_xor_sync(~0u, tm, 2);
        tm += __shfl_xor_sync(~0u, tm, 4);
        if (l8 == 0) {
            g_psu[(h * N + rg) * 16 + blockIdx.x] = tt - tm;
            g_psm[(h * N + rg) * 16 + blockIdx.x] = tm;
        }
    }
    #pragma unroll
    for (int o = 16; o > 0; o >>= 1)
        lmin = fminf(lmin, __shfl_xor_sync(~0u, lmin, o));
    if (lane == 0) red[w] = lmin;
    __syncthreads();
    if (tid == 0) {
        float m = red[0];
        #pragma unroll
        for (int i = 1; i < 8; i++) m = fminf(m, red[i]);
        atomicMin(&g_smin_enc, enc_f(m));
    }
}

// rinv[h][n] = 1 / (sum_unmasked + exp(smin) * sum_masked)
__global__ void rinv_kernel() {
    int idx = blockIdx.x * 256 + threadIdx.x;
    float es = __expf(dec_f(g_smin_enc));
    float a = 0.f, b = 0.f;
    #pragma unroll
    for (int t = 0; t < 16; t++) {
        a += g_psu[idx * 16 + t];
        b += g_psm[idx * 16 + t];
    }
    g_rinv[idx] = 1.0f / (a + es * b);
}

__global__ __launch_bounds__(256) void mean_kernel(
    const float* __restrict__ S, const void* __restrict__ mask,
    float* __restrict__ out2)
{
    int idx = blockIdx.x * 256 + threadIdx.x;
    const unsigned mo = g_mask_or;
    float smin = dec_f(g_smin_enc);
    float s = 0.0f;
    #pragma unroll
    for (int h = 0; h < HH; h++) s += S[h * NN + idx];
    out2[idx] = s * 0.125f + smin * mask_not(mask, idx, mo);
}

// PV (FFMA2): x[(d*8+h)][n] = sum_m P v, P = E*(1+notm*(es-1))*rinv[n]
__global__ __launch_bounds__(128) void pv_kernel(
    const float* __restrict__ E, const float* __restrict__ v,
    const void* __restrict__ mask,
    float* __restrict__ X1, float* __restrict__ X2)
{
    __shared__ float As[2][16][64];
    __shared__ float Bs[2][16][132];
    __shared__ float ri[128];
    const int tid = threadIdx.x, tx = tid & 15, ty = tid >> 4;
    const int n0 = blockIdx.x * 128;
    const int mbase = blockIdx.y * (N / 2);
    const int h = blockIdx.z;
    float* O = blockIdx.y ? X2 : X1;

    ri[tid] = g_rinv[h * N + n0 + tid];
    const unsigned mo = g_mask_or;
    const float esm1 = __expf(dec_f(g_smin_enc)) - 1.0f;

    ull acc[8][4];
    #pragma unroll
    for (int i = 0; i < 8; i++)
        #pragma unroll
        for (int j = 0; j < 4; j++) acc[i][j] = 0ull;

    const int ad = tid >> 1, am8 = (tid & 1) * 8;
    const float* Vp = v + (ad * HH + h) * N + mbase + am8;
    const float* Sb = E + h * NN + n0 * N + mbase;

    float4 ra0, ra1, rb[4];
    ra0 = *(const float4*)(Vp);
    ra1 = *(const float4*)(Vp + 4);
    #pragma unroll
    for (int i = 0; i < 4; i++) {
        int idx = tid + i * 128;
        int nn = idx >> 2, mq = idx & 3;
        rb[i] = *(const float4*)(Sb + nn * N + mq * 4);
    }
    __syncthreads();
    {
        As[0][am8 + 0][ad] = ra0.x; As[0][am8 + 1][ad] = ra0.y;
        As[0][am8 + 2][ad] = ra0.z; As[0][am8 + 3][ad] = ra0.w;
        As[0][am8 + 4][ad] = ra1.x; As[0][am8 + 5][ad] = ra1.y;
        As[0][am8 + 6][ad] = ra1.z; As[0][am8 + 7][ad] = ra1.w;
        #pragma unroll
        for (int i = 0; i < 4; i++) {
            int idx = tid + i * 128;
            int nn = idx >> 2, mq = idx & 3;
            float4 nm = mask_not4(mask, (n0 + nn) * N + mbase + mq * 4, mo);
            float RI = ri[nn];
            Bs[0][mq * 4 + 0][nn] = rb[i].x * fmaf(nm.x, esm1, 1.f) * RI;
            Bs[0][mq * 4 + 1][nn] = rb[i].y * fmaf(nm.y, esm1, 1.f) * RI;
            Bs[0][mq * 4 + 2][nn] = rb[i].z * fmaf(nm.z, esm1, 1.f) * RI;
            Bs[0][mq * 4 + 3][nn] = rb[i].w * fmaf(nm.w, esm1, 1.f) * RI;
        }
    }
    __syncthreads();

    const int KT = (N / 2) / 16;
    for (int kt = 0; kt < KT; kt++) {
        const int s = kt & 1;
        const int c1 = (kt + 1) * 16;
        if (kt + 1 < KT) {
            ra0 = *(const float4*)(Vp + c1);
            ra1 = *(const float4*)(Vp + c1 + 4);
            #pragma unroll
            for (int i = 0; i < 4; i++) {
                int idx = tid + i * 128;
                int nn = idx >> 2, mq = idx & 3;
                rb[i] = *(const float4*)(Sb + nn * N + c1 + mq * 4);
            }
        }
        gemm16(As[s], Bs[s], acc, tx, ty);
        if (kt + 1 < KT) {
            const int d = s ^ 1;
            As[d][am8 + 0][ad] = ra0.x; As[d][am8 + 1][ad] = ra0.y;
            As[d][am8 + 2][ad] = ra0.z; As[d][am8 + 3][ad] = ra0.w;
            As[d][am8 + 4][ad] = ra1.x; As[d][am8 + 5][ad] = ra1.y;
            As[d][am8 + 6][ad] = ra1.z; As[d][am8 + 7][ad] = ra1.w;
            #pragma unroll
            for (int i = 0; i < 4; i++) {
                int idx = tid + i * 128;
                int nn = idx >> 2, mq = idx & 3;
                float4 nm = mask_not4(mask, (n0 + nn) * N + mbase + c1 + mq * 4, mo);
                float RI = ri[nn];
                Bs[d][mq * 4 + 0][nn] = rb[i].x * fmaf(nm.x, esm1, 1.f) * RI;
                Bs[d][mq * 4 + 1][nn] = rb[i].y * fmaf(nm.y, esm1, 1.f) * RI;
                Bs[d][mq * 4 + 2][nn] = rb[i].z * fmaf(nm.z, esm1, 1.f) * RI;
                Bs[d][mq * 4 + 3][nn] = rb[i].w * fmaf(nm.w, esm1, 1.f) * RI;
            }
        }
        __syncthreads();
    }

    #pragma unroll
    for (int i = 0; i < 8; i++) {
        float2 v0 = up2(acc[i][0]), v1 = up2(acc[i][1]);
        float2 v2 = up2(acc[i][2]), v3 = up2(acc[i][3]);
        float4 o0 = {v0.x, v0.y, v1.x, v1.y};
        float4 o1 = {v2.x, v2.y, v3.x, v3.y};
        float* row = O + ((ty * 8 + i) * HH + h) * N + n0;
        *(float4*)(row + tx * 4) = o0;
        *(float4*)(row + 64 + tx * 4) = o1;
    }
}

// Merge projection: out = Wm @ (x1 + x2) + bm
__global__ __launch_bounds__(128) void merge_kernel(
    const float* __restrict__ W, const float* __restrict__ bm,
    const float* __restrict__ X1, const float* __restrict__ X2,
    float* __restrict__ O)
{
    __shared__ float As[2][16][64];
    __shared__ float Bs[2][16][132];
    const int tid = threadIdx.x, tx = tid & 15, ty = tid >> 4;
    const int n0 = blockIdx.x * 128, m0 = blockIdx.y * 64;

    ull acc[8][4];
    #pragma unroll
    for (int i = 0; i < 8; i++)
        #pragma unroll
        for (int j = 0; j < 4; j++) acc[i][j] = 0ull;

    const int ao = tid >> 1, ac = (tid & 1) * 8;
    const float* Ap = W + (m0 + ao) * DM + ac;
    const int brow = tid >> 5, bc4 = tid & 31;
    const float* B1 = X1 + brow * N + n0 + bc4 * 4;
    const float* B2 = X2 + brow * N + n0 + bc4 * 4;

    float4 ra0, ra1, rb[4];
    ra0 = *(const float4*)(Ap);
    ra1 = *(const float4*)(Ap + 4);
    #pragma unroll
    for (int i = 0; i < 4; i++) {
        float4 a = *(const float4*)(B1 + (i * 4) * N);
        float4 b = *(const float4*)(B2 + (i * 4) * N);
        rb[i] = make_float4(a.x + b.x, a.y + b.y, a.z + b.z, a.w + b.w);
    }
    {
        As[0][ac + 0][ao] = ra0.x; As[0][ac + 1][ao] = ra0.y;
        As[0][ac + 2][ao] = ra0.z; As[0][ac + 3][ao] = ra0.w;
        As[0][ac + 4][ao] = ra1.x; As[0][ac + 5][ao] = ra1.y;
        As[0][ac + 6][ao] = ra1.z; As[0][ac + 7][ao] = ra1.w;
        #pragma unroll
        for (int i = 0; i < 4; i++)
            *(float4*)&Bs[0][brow + i * 4][bc4 * 4] = rb[i];
    }
    __syncthreads();

    const int KT = DM / 16;
    for (int kt = 0; kt < KT; kt++) {
        const int s = kt & 1;
        if (kt + 1 < KT) {
            const int c0 = (kt + 1) * 16;
            ra0 = *(const float4*)(Ap + c0);
            ra1 = *(const float4*)(Ap + c0 + 4);
            #pragma unroll
            for (int i = 0; i < 4; i++) {
                float4 a = *(const float4*)(B1 + (c0 + i * 4) * N);
                float4 b = *(const float4*)(B2 + (c0 + i * 4) * N);
                rb[i] = make_float4(a.x + b.x, a.y + b.y, a.z + b.z, a.w + b.w);
            }
        }
        gemm16(As[s], Bs[s], acc, tx, ty);
        if (kt + 1 < KT) {
            const int d = s ^ 1;
            As[d][ac + 0][ao] = ra0.x; As[d][ac + 1][ao] = ra0.y;
            As[d][ac + 2][ao] = ra0.z; As[d][ac + 3][ao] = ra0.w;
            As[d][ac + 4][ao] = ra1.x; As[d][ac + 5][ao] = ra1.y;
            As[d][ac + 6][ao] = ra1.z; As[d][ac + 7][ao] = ra1.w;
            #pragma unroll
            for (int i = 0; i < 4; i++)
                *(float4*)&Bs[d][brow + i * 4][bc4 * 4] = rb[i];
        }
        __syncthreads();
    }

    #pragma unroll
    for (int i = 0; i < 8; i++) {
        float bias = bm[m0 + ty * 8 + i];
        float2 v0 = up2(acc[i][0]), v1 = up2(acc[i][1]);
        float2 v2 = up2(acc[i][2]), v3 = up2(acc[i][3]);
        float4 o0 = {v0.x + bias, v0.y + bias, v1.x + bias, v1.y + bias};
        float4 o1 = {v2.x + bias, v2.y + bias, v3.x + bias, v3.y + bias};
        float* row = O + (m0 + ty * 8 + i) * N + n0;
        *(float4*)(row + tx * 4) = o0;
        *(float4*)(row + 64 + tx * 4) = o1;
    }
}

// ---------------- launch ----------------
extern "C" void kernel_launch(void* const* d_in, const int* in_sizes, int n_in,
                              void* d_out, int out_size) {
    const float* query = (const float*)d_in[0];
    const float* key   = (const float*)d_in[1];
    const float* value = (const float*)d_in[2];
    const void*  mask  = d_in[4];
    const float* Wq = (const float*)d_in[5];
    const float* bq = (const float*)d_in[6];
    const float* Wk = (const float*)d_in[7];
    const float* bk = (const float*)d_in[8];
    const float* Wv = (const float*)d_in[9];
    const float* bv = (const float*)d_in[10];
    const float* Wm = (const float*)d_in[11];
    const float* bm = (const float*)d_in[12];
    float* out = (float*)d_out;

    float *qp, *kp, *vp, *x1p, *x2p, *Sp, *Ep;
    cudaGetSymbolAddress((void**)&qp, g_q);
    cudaGetSymbolAddress((void**)&kp, g_k);
    cudaGetSymbolAddress((void**)&vp, g_v);
    cudaGetSymbolAddress((void**)&x1p, g_x1);
    cudaGetSymbolAddress((void**)&x2p, g_x2);
    cudaGetSymbolAddress((void**)&Sp, g_S);
    cudaGetSymbolAddress((void**)&Ep, g_E);

    cudaFuncSetAttribute(scores_mma_kernel,
                         cudaFuncAttributeMaxDynamicSharedMemorySize, SMTOT);

    init_kernel<<<1, 1>>>();
    mask_detect_kernel<<<128, 256>>>((const unsigned*)mask);

    qkv_kernel<<<dim3(N / 128, DM / 64, 3), 128>>>(
        Wq, Wk, Wv, bq, bk, bv, query, key, value, qp, kp, vp);

    scores_mma_kernel<<<dim3(16, 16, HH), 256, SMTOT>>>(qp, kp, mask, Sp, Ep);

    rinv_kernel<<<HH * N / 256, 256>>>();
    mean_kernel<<<NN / 256, 256>>>(Sp, mask, out + DM * N);

    pv_kernel<<<dim3(16, 2, HH), 128>>>(Ep, vp, mask, x1p, x2p);

    merge_kernel<<<dim3(N / 128, DM / 64), 128>>>(Wm, bm, x1p, x2p, out);
}

// round 17
// speedup vs baseline: 1.9191x; 1.1467x over previous
#include <cuda_runtime.h>
#include <cuda_fp16.h>
#include <cstdint>

#define N      2048
#define DM     512
#define HH     8
#define NN     (N * N)

typedef unsigned long long ull;
typedef unsigned short us;

// ---------------- device scratch ----------------
__device__ float    g_q[DM * N];
__device__ float    g_k[DM * N];
__device__ us       g_vh[DM * N];      // V as fp16
__device__ float    g_x1[DM * N];
__device__ float    g_x2[DM * N];
__device__ float    g_S[HH * NN];
__device__ us       g_Eh[HH * NN];     // exp(S) fp16
__device__ us       g_EMh[HH * NN];    // exp(S)*notm fp16
__device__ float    g_psu[HH * N * 16];
__device__ float    g_psm[HH * N * 16];
__device__ float    g_rinv[HH * N];
__device__ unsigned g_smin_enc;
__device__ unsigned g_mask_or;

// ---------------- helpers ----------------
__device__ __forceinline__ unsigned enc_f(float x) {
    unsigned u = __float_as_uint(x);
    return (u & 0x80000000u) ? ~u : (u | 0x80000000u);
}
__device__ __forceinline__ float dec_f(unsigned u) {
    return (u & 0x80000000u) ? __uint_as_float(u & 0x7FFFFFFFu)
                             : __uint_as_float(~u);
}
__device__ __forceinline__ float mask_not(const void* mask, int i, unsigned o) {
    bool mv;
    if (o == 0x3F800000u)      mv = ((const float*)mask)[i] != 0.0f;
    else if (o == 1u)          mv = ((const int*)mask)[i] != 0;
    else                       mv = ((const unsigned char*)mask)[i] != 0;
    return mv ? 0.0f : 1.0f;
}
__device__ __forceinline__ float4 mask_not4(const void* mask, int i, unsigned o) {
    float4 r;
    if (o == 0x3F800000u) {
        float4 m = *(const float4*)((const float*)mask + i);
        r.x = m.x != 0.0f ? 0.f : 1.f; r.y = m.y != 0.0f ? 0.f : 1.f;
        r.z = m.z != 0.0f ? 0.f : 1.f; r.w = m.w != 0.0f ? 0.f : 1.f;
    } else if (o == 1u) {
        int4 m = *(const int4*)((const int*)mask + i);
        r.x = m.x ? 0.f : 1.f; r.y = m.y ? 0.f : 1.f;
        r.z = m.z ? 0.f : 1.f; r.w = m.w ? 0.f : 1.f;
    } else {
        uchar4 m = *(const uchar4*)((const unsigned char*)mask + i);
        r.x = m.x ? 0.f : 1.f; r.y = m.y ? 0.f : 1.f;
        r.z = m.z ? 0.f : 1.f; r.w = m.w ? 0.f : 1.f;
    }
    return r;
}
__device__ __forceinline__ void ffma2(ull& d, ull a, ull b) {
    asm("fma.rn.f32x2 %0, %1, %2, %0;" : "+l"(d) : "l"(a), "l"(b));
}
__device__ __forceinline__ ull pk2(float x, float y) {
    ull r; asm("mov.b64 %0, {%1, %2};" : "=l"(r) : "f"(x), "f"(y)); return r;
}
__device__ __forceinline__ float2 up2(ull p) {
    float2 r; asm("mov.b64 {%0, %1}, %2;" : "=f"(r.x), "=f"(r.y) : "l"(p)); return r;
}
__device__ __forceinline__ uint32_t smem_u32(const void* p) {
    uint32_t a;
    asm("{ .reg .u64 t; cvta.to.shared.u64 t, %1; cvt.u32.u64 %0, t; }"
        : "=r"(a) : "l"(p));
    return a;
}
__device__ __forceinline__ unsigned pkbf(float a, float b) {
    unsigned r; asm("cvt.rn.bf16x2.f32 %0, %1, %2;" : "=r"(r) : "f"(b), "f"(a));
    return r;
}
__device__ __forceinline__ unsigned pkh(float a, float b) {
    unsigned r; asm("cvt.rn.f16x2.f32 %0, %1, %2;" : "=r"(r) : "f"(b), "f"(a));
    return r;
}
__device__ __forceinline__ void ldsm4(unsigned* r, uint32_t a) {
    asm volatile("ldmatrix.sync.aligned.m8n8.x4.shared.b16 {%0,%1,%2,%3}, [%4];"
        : "=r"(r[0]), "=r"(r[1]), "=r"(r[2]), "=r"(r[3]) : "r"(a));
}
__device__ __forceinline__ void mma16816(float* c, const unsigned* a,
                                         unsigned b0, unsigned b1) {
    asm volatile(
        "mma.sync.aligned.m16n8k16.row.col.f32.bf16.bf16.f32 "
        "{%0,%1,%2,%3}, {%4,%5,%6,%7}, {%8,%9}, {%0,%1,%2,%3};"
        : "+f"(c[0]), "+f"(c[1]), "+f"(c[2]), "+f"(c[3])
        : "r"(a[0]), "r"(a[1]), "r"(a[2]), "r"(a[3]), "r"(b0), "r"(b1));
}
__device__ __forceinline__ void mma16816h(float* c, const unsigned* a,
                                          unsigned b0, unsigned b1) {
    asm volatile(
        "mma.sync.aligned.m16n8k16.row.col.f32.f16.f16.f32 "
        "{%0,%1,%2,%3}, {%4,%5,%6,%7}, {%8,%9}, {%0,%1,%2,%3};"
        : "+f"(c[0]), "+f"(c[1]), "+f"(c[2]), "+f"(c[3])
        : "r"(a[0]), "r"(a[1]), "r"(a[2]), "r"(a[3]), "r"(b0), "r"(b1));
}

// ---------------- small kernels ----------------
__global__ void init_kernel() { g_smin_enc = 0xFFFFFFFFu; g_mask_or = 0u; }

__global__ void mask_detect_kernel(const unsigned* __restrict__ m) {
    __shared__ unsigned sh[256];
    unsigned acc = 0;
    const int total = NN / 4;
    for (int i = blockIdx.x * blockDim.x + threadIdx.x; i < total;
         i += gridDim.x * blockDim.x) acc |= m[i];
    sh[threadIdx.x] = acc;
    __syncthreads();
    for (int s = 128; s > 0; s >>= 1) {
        if (threadIdx.x < s) sh[threadIdx.x] |= sh[threadIdx.x + s];
        __syncthreads();
    }
    if (threadIdx.x == 0) atomicOr(&g_mask_or, sh[0]);
}

// ---------------- FFMA2 GEMM core (qkv / merge) ----------------
__device__ __forceinline__ void gemm16(const float (*__restrict__ As)[64],
                                       const float (*__restrict__ Bs)[132],
                                       ull acc[8][4], int tx, int ty) {
    #pragma unroll
    for (int k = 0; k < 16; k++) {
        float4 a0 = *(const float4*)&As[k][ty * 8];
        float4 a1 = *(const float4*)&As[k][ty * 8 + 4];
        float4 b0 = *(const float4*)&Bs[k][tx * 4];
        float4 b1 = *(const float4*)&Bs[k][64 + tx * 4];
        ull pb0 = pk2(b0.x, b0.y), pb1 = pk2(b0.z, b0.w);
        ull pb2 = pk2(b1.x, b1.y), pb3 = pk2(b1.z, b1.w);
        float av[8] = {a0.x, a0.y, a0.z, a0.w, a1.x, a1.y, a1.z, a1.w};
        #pragma unroll
        for (int i = 0; i < 8; i++) {
            ull pa = pk2(av[i], av[i]);
            ffma2(acc[i][0], pa, pb0);
            ffma2(acc[i][1], pa, pb1);
            ffma2(acc[i][2], pa, pb2);
            ffma2(acc[i][3], pa, pb3);
        }
    }
}

__global__ __launch_bounds__(128) void qkv_kernel(
    const float* __restrict__ Wq, const float* __restrict__ Wk,
    const float* __restrict__ Wv, const float* __restrict__ bq,
    const float* __restrict__ bk, const float* __restrict__ bv,
    const float* __restrict__ Xq, const float* __restrict__ Xk,
    const float* __restrict__ Xv,
    float* __restrict__ Oq, float* __restrict__ Ok, us* __restrict__ Ovh)
{
    const float *W, *Bv_, *X;
    float* O = Oq;
    if (blockIdx.z == 0)      { W = Wq; Bv_ = bq; X = Xq; O = Oq; }
    else if (blockIdx.z == 1) { W = Wk; Bv_ = bk; X = Xk; O = Ok; }
    else                      { W = Wv; Bv_ = bv; X = Xv; }

    __shared__ float As[2][16][64];
    __shared__ float Bs[2][16][132];
    const int tid = threadIdx.x, tx = tid & 15, ty = tid >> 4;
    const int n0 = blockIdx.x * 128, m0 = blockIdx.y * 64;

    ull acc[8][4];
    #pragma unroll
    for (int i = 0; i < 8; i++)
        #pragma unroll
        for (int j = 0; j < 4; j++) acc[i][j] = 0ull;

    const int ao = tid >> 1, ac = (tid & 1) * 8;
    const float* Ap = W + (m0 + ao) * DM + ac;
    const int brow = tid >> 5, bc4 = tid & 31;
    const float* Bp = X + brow * N + n0 + bc4 * 4;

    float4 ra0, ra1, rb[4];
    ra0 = *(const float4*)(Ap);
    ra1 = *(const float4*)(Ap + 4);
    #pragma unroll
    for (int i = 0; i < 4; i++)
        rb[i] = *(const float4*)(Bp + (i * 4) * N);
    {
        As[0][ac + 0][ao] = ra0.x; As[0][ac + 1][ao] = ra0.y;
        As[0][ac + 2][ao] = ra0.z; As[0][ac + 3][ao] = ra0.w;
        As[0][ac + 4][ao] = ra1.x; As[0][ac + 5][ao] = ra1.y;
        As[0][ac + 6][ao] = ra1.z; As[0][ac + 7][ao] = ra1.w;
        #pragma unroll
        for (int i = 0; i < 4; i++)
            *(float4*)&Bs[0][brow + i * 4][bc4 * 4] = rb[i];
    }
    __syncthreads();

    const int KT = DM / 16;
    for (int kt = 0; kt < KT; kt++) {
        const int s = kt & 1;
        if (kt + 1 < KT) {
            const int c0 = (kt + 1) * 16;
            ra0 = *(const float4*)(Ap + c0);
            ra1 = *(const float4*)(Ap + c0 + 4);
            #pragma unroll
            for (int i = 0; i < 4; i++)
                rb[i] = *(const float4*)(Bp + (c0 + i * 4) * N);
        }
        gemm16(As[s], Bs[s], acc, tx, ty);
        if (kt + 1 < KT) {
            const int d = s ^ 1;
            As[d][ac + 0][ao] = ra0.x; As[d][ac + 1][ao] = ra0.y;
            As[d][ac + 2][ao] = ra0.z; As[d][ac + 3][ao] = ra0.w;
            As[d][ac + 4][ao] = ra1.x; As[d][ac + 5][ao] = ra1.y;
            As[d][ac + 6][ao] = ra1.z; As[d][ac + 7][ao] = ra1.w;
            #pragma unroll
            for (int i = 0; i < 4; i++)
                *(float4*)&Bs[d][brow + i * 4][bc4 * 4] = rb[i];
        }
        __syncthreads();
    }

    #pragma unroll
    for (int i = 0; i < 8; i++) {
        float bias = Bv_[m0 + ty * 8 + i];
        float2 v0 = up2(acc[i][0]), v1 = up2(acc[i][1]);
        float2 v2 = up2(acc[i][2]), v3 = up2(acc[i][3]);
        float4 o0 = {v0.x + bias, v0.y + bias, v1.x + bias, v1.y + bias};
        float4 o1 = {v2.x + bias, v2.y + bias, v3.x + bias, v3.y + bias};
        if (blockIdx.z == 2) {
            us* rowh = Ovh + (m0 + ty * 8 + i) * N + n0;
            uint2 p0 = {pkh(o0.x, o0.y), pkh(o0.z, o0.w)};
            uint2 p1 = {pkh(o1.x, o1.y), pkh(o1.z, o1.w)};
            *(uint2*)(rowh + tx * 4) = p0;
            *(uint2*)(rowh + 64 + tx * 4) = p1;
        } else {
            float* row = O + (m0 + ty * 8 + i) * N + n0;
            *(float4*)(row + tx * 4) = o0;
            *(float4*)(row + 64 + tx * 4) = o1;
        }
    }
}

// -------- scores via mma.sync bf16 3-pass: 128n x 128m per CTA, K=64 -------
#define SPITCH 144
#define SM_QH 0
#define SM_QL 18432
#define SM_KH 36864
#define SM_KL 55296
#define SMTOT 73792

__global__ __launch_bounds__(256) void scores_mma_kernel(
    const float* __restrict__ qg, const float* __restrict__ kg,
    const void* __restrict__ mask,
    float* __restrict__ S, us* __restrict__ Eh, us* __restrict__ EMh)
{
    extern __shared__ char sm[];
    __shared__ float red[8];
    float* TBf = (float*)sm;   // epilogue reuse of staging as 128x132 f32
    const int tid = threadIdx.x, lane = tid & 31, w = tid >> 5;
    const int wn = w & 3, wm = w >> 2;
    const int m0g = blockIdx.x * 128, n0g = blockIdx.y * 128;
    const int h = blockIdx.z;
    const uint32_t sb = smem_u32(sm);
    const int r8 = lane & 7, jm = lane >> 3;
    const int l8 = lane & 7, l8g = lane >> 3;

    // stage q,k as bf16 hi/lo, [row][d] pitch 144B
    {
        const int n = tid & 127, dg = tid >> 7;
        #pragma unroll 4
        for (int i = 0; i < 16; i++) {
            const int d = i * 4 + dg * 2;
            float q0 = qg[(d * HH + h) * N + n0g + n];
            float q1 = qg[((d + 1) * HH + h) * N + n0g + n];
            float k0 = kg[(d * HH + h) * N + m0g + n];
            float k1 = kg[((d + 1) * HH + h) * N + m0g + n];
            unsigned qh = pkbf(q0, q1);
            unsigned kh = pkbf(k0, k1);
            unsigned ql = pkbf(q0 - __uint_as_float(qh << 16),
                               q1 - __uint_as_float(qh & 0xFFFF0000u));
            unsigned kl = pkbf(k0 - __uint_as_float(kh << 16),
                               k1 - __uint_as_float(kh & 0xFFFF0000u));
            const int off = n * SPITCH + d * 2;
            *(unsigned*)(sm + SM_QH + off) = qh;
            *(unsigned*)(sm + SM_QL + off) = ql;
            *(unsigned*)(sm + SM_KH + off) = kh;
            *(unsigned*)(sm + SM_KL + off) = kl;
        }
    }
    __syncthreads();

    float c[2][8][4];
    #pragma unroll
    for (int a = 0; a < 2; a++)
        #pragma unroll
        for (int b = 0; b < 8; b++)
            #pragma unroll
            for (int d = 0; d < 4; d++) c[a][b][d] = 0.0f;

    #pragma unroll
    for (int ks = 0; ks < 4; ks++) {
        unsigned ah[2][4], al[2][4], bh[4][4], bl[4][4];
        #pragma unroll
        for (int na = 0; na < 2; na++) {
            uint32_t ad = sb + SM_QH
                + (wn * 32 + na * 16 + (jm & 1) * 8 + r8) * SPITCH
                + ks * 32 + (jm >> 1) * 16;
            ldsm4(ah[na], ad);
            ldsm4(al[na], ad + (SM_QL - SM_QH));
        }
        #pragma unroll
        for (int p = 0; p < 4; p++) {
            uint32_t bd = sb + SM_KH
                + (wm * 64 + p * 16 + (jm >> 1) * 8 + r8) * SPITCH
                + ks * 32 + (jm & 1) * 16;
            ldsm4(bh[p], bd);
            ldsm4(bl[p], bd + (SM_KL - SM_KH));
        }
        #pragma unroll
        for (int na = 0; na < 2; na++)
            #pragma unroll
            for (int ma = 0; ma < 8; ma++) {
                const int p = ma >> 1, s2 = (ma & 1) * 2;
                mma16816(c[na][ma], ah[na], bh[p][s2], bh[p][s2 + 1]);
                mma16816(c[na][ma], al[na], bh[p][s2], bh[p][s2 + 1]);
                mma16816(c[na][ma], ah[na], bl[p][s2], bl[p][s2 + 1]);
            }
    }
    __syncthreads();

    // fragments -> smem transpose buffer
    #pragma unroll
    for (int na = 0; na < 2; na++)
        #pragma unroll
        for (int ma = 0; ma < 8; ma++) {
            const int rr = wn * 32 + na * 16 + (lane >> 2);
            const int cc = wm * 64 + ma * 8 + (lane & 3) * 2;
            float2 lo = {c[na][ma][0], c[na][ma][1]};
            float2 hi = {c[na][ma][2], c[na][ma][3]};
            *(float2*)&TBf[rr * 132 + cc] = lo;
            *(float2*)&TBf[(rr + 8) * 132 + cc] = hi;
        }
    __syncthreads();

    // coalesced epilogue: S f32, E/EM fp16, row partials, global min
    const unsigned mo = g_mask_or;
    float lmin = 3.0e38f;
    float* Sb = S + h * NN;
    us* Eb = Eh + h * NN;
    us* EMb = EMh + h * NN;
    #pragma unroll
    for (int i = 0; i < 4; i++) {
        const int r = w * 16 + i * 4 + l8g;
        const int rg = n0g + r;
        float tt = 0.f, tm = 0.f;
        #pragma unroll
        for (int cc = 0; cc < 4; cc++) {
            const int col = cc * 32 + l8 * 4;
            float4 s4 = *(float4*)&TBf[r * 132 + col];
            s4.x *= 0.125f; s4.y *= 0.125f; s4.z *= 0.125f; s4.w *= 0.125f;
            lmin = fminf(lmin, fminf(fminf(s4.x, s4.y), fminf(s4.z, s4.w)));
            *(float4*)(Sb + rg * N + m0g + col) = s4;
            float4 e4 = {__expf(s4.x), __expf(s4.y), __expf(s4.z), __expf(s4.w)};
            float4 nm = mask_not4(mask, rg * N + m0g + col, mo);
            float4 em4 = {e4.x * nm.x, e4.y * nm.y, e4.z * nm.z, e4.w * nm.w};
            uint2 pe = {pkh(e4.x, e4.y), pkh(e4.z, e4.w)};
            uint2 pm = {pkh(em4.x, em4.y), pkh(em4.z, em4.w)};
            *(uint2*)(Eb + rg * N + m0g + col) = pe;
            *(uint2*)(EMb + rg * N + m0g + col) = pm;
            tm += em4.x + em4.y + em4.z + em4.w;
            tt += e4.x + e4.y + e4.z + e4.w;
        }
        tt += __shfl_xor_sync(~0u, tt, 1);
        tt += __shfl_xor_sync(~0u, tt, 2);
        tt += __shfl_xor_sync(~0u, tt, 4);
        tm += __shfl_xor_sync(~0u, tm, 1);
        tm += __shfl_xor_sync(~0u, tm, 2);
        tm += __shfl_xor_sync(~0u, tm, 4);
        if (l8 == 0) {
            g_psu[(h * N + rg) * 16 + blockIdx.x] = tt - tm;
            g_psm[(h * N + rg) * 16 + blockIdx.x] = tm;
        }
    }
    #pragma unroll
    for (int o = 16; o > 0; o >>= 1)
        lmin = fminf(lmin, __shfl_xor_sync(~0u, lmin, o));
    if (lane == 0) red[w] = lmin;
    __syncthreads();
    if (tid == 0) {
        float m = red[0];
        #pragma unroll
        for (int i = 1; i < 8; i++) m = fminf(m, red[i]);
        atomicMin(&g_smin_enc, enc_f(m));
    }
}

// rinv[h][n] = 1 / (sum_unmasked + exp(smin) * sum_masked)
__global__ void rinv_kernel() {
    int idx = blockIdx.x * 256 + threadIdx.x;
    float es = __expf(dec_f(g_smin_enc));
    float a = 0.f, b = 0.f;
    #pragma unroll
    for (int t = 0; t < 16; t++) {
        a += g_psu[idx * 16 + t];
        b += g_psm[idx * 16 + t];
    }
    g_rinv[idx] = 1.0f / (a + es * b);
}

__global__ __launch_bounds__(256) void mean_kernel(
    const float* __restrict__ S, const void* __restrict__ mask,
    float* __restrict__ out2)
{
    int idx = blockIdx.x * 256 + threadIdx.x;
    const unsigned mo = g_mask_or;
    float smin = dec_f(g_smin_enc);
    float s = 0.0f;
    #pragma unroll
    for (int h = 0; h < HH; h++) s += S[h * NN + idx];
    out2[idx] = s * 0.125f + smin * mask_not(mask, idx, mo);
}

// -------- PV via fp16 mma.sync, zero-conversion staging --------------------
// tile: 64d x 128n per CTA, grid (16 ntiles, 2 msplit, 8 h), 256 thr.
// stage: V 64x144 | E 128x144 | EM 128x144 = 46080 B; double-buffered.
#define PV_V  0
#define PV_E  9216
#define PV_M  27648
#define PV_STG 46080
#define PV_TOT (2 * PV_STG)

__global__ __launch_bounds__(256) void pv_f16_kernel(
    const us* __restrict__ Eh, const us* __restrict__ EMh,
    const us* __restrict__ vh,
    float* __restrict__ X1, float* __restrict__ X2)
{
    extern __shared__ char dsm[];
    __shared__ float ri[128];
    const int tid = threadIdx.x, lane = tid & 31, w = tid >> 5;
    const int wd = w & 3, wn = w >> 2;
    const int n0 = blockIdx.x * 128, h = blockIdx.z;
    const int mbase = blockIdx.y * (N / 2);
    float* X = blockIdx.y ? X2 : X1;
    const uint32_t sb = smem_u32(dsm);
    const float esm1 = __expf(dec_f(g_smin_enc)) - 1.0f;
    const int r8 = lane & 7, jm = lane >> 3;

    if (tid < 128) ri[tid] = g_rinv[h * N + n0 + tid];

    float cE[8][4], cM[8][4];
    #pragma unroll
    for (int f = 0; f < 8; f++)
        #pragma unroll
        for (int j = 0; j < 4; j++) { cE[f][j] = 0.f; cM[f][j] = 0.f; }

    const us* Ebase = Eh + h * NN;
    const us* Mbase = EMh + h * NN;

    uint4 rv[2], re[4], rm[4];
    {
        const int m0 = mbase;
        #pragma unroll
        for (int i = 0; i < 2; i++) {
            int idx = tid + i * 256, row = idx >> 3, c16 = idx & 7;
            rv[i] = *(const uint4*)(vh + (row * HH + h) * N + m0 + c16 * 8);
        }
        #pragma unroll
        for (int i = 0; i < 4; i++) {
            int idx = tid + i * 256, row = idx >> 3, c16 = idx & 7;
            re[i] = *(const uint4*)(Ebase + (n0 + row) * N + m0 + c16 * 8);
            rm[i] = *(const uint4*)(Mbase + (n0 + row) * N + m0 + c16 * 8);
        }
    }
    #pragma unroll
    for (int i = 0; i < 2; i++) {
        int idx = tid + i * 256, row = idx >> 3, c16 = idx & 7;
        *(uint4*)(dsm + PV_V + row * SPITCH + c16 * 16) = rv[i];
    }
    #pragma unroll
    for (int i = 0; i < 4; i++) {
        int idx = tid + i * 256, row = idx >> 3, c16 = idx & 7;
        *(uint4*)(dsm + PV_E + row * SPITCH + c16 * 16) = re[i];
        *(uint4*)(dsm + PV_M + row * SPITCH + c16 * 16) = rm[i];
    }
    __syncthreads();

    for (int mc = 0; mc < 16; mc++) {
        const int s = mc & 1;
        const uint32_t stg = sb + s * PV_STG;
        if (mc + 1 < 16) {
            const int m0 = mbase + (mc + 1) * 64;
            #pragma unroll
            for (int i = 0; i < 2; i++) {
                int idx = tid + i * 256, row = idx >> 3, c16 = idx & 7;
                rv[i] = *(const uint4*)(vh + (row * HH + h) * N + m0 + c16 * 8);
            }
            #pragma unroll
            for (int i = 0; i < 4; i++) {
                int idx = tid + i * 256, row = idx >> 3, c16 = idx & 7;
                re[i] = *(const uint4*)(Ebase + (n0 + row) * N + m0 + c16 * 8);
                rm[i] = *(const uint4*)(Mbase + (n0 + row) * N + m0 + c16 * 8);
            }
        }
        #pragma unroll
        for (int ks = 0; ks < 4; ks++) {
            unsigned a4[4], bf[4][4];
            uint32_t ad = stg + PV_V
                + (wd * 16 + (jm & 1) * 8 + r8) * SPITCH
                + ks * 32 + (jm >> 1) * 16;
            ldsm4(a4, ad);
            #pragma unroll
            for (int p = 0; p < 4; p++) {
                uint32_t bd = stg + PV_E
                    + (wn * 64 + p * 16 + (jm >> 1) * 8 + r8) * SPITCH
                    + ks * 32 + (jm & 1) * 16;
                ldsm4(bf[p], bd);
            }
            #pragma unroll
            for (int p = 0; p < 4; p++)
                #pragma unroll
                for (int q = 0; q < 2; q++)
                    mma16816h(cE[p * 2 + q], a4, bf[p][q * 2], bf[p][q * 2 + 1]);
            #pragma unroll
            for (int p = 0; p < 4; p++) {
                uint32_t bd = stg + PV_M
                    + (wn * 64 + p * 16 + (jm >> 1) * 8 + r8) * SPITCH
                    + ks * 32 + (jm & 1) * 16;
                ldsm4(bf[p], bd);
            }
            #pragma unroll
            for (int p = 0; p < 4; p++)
                #pragma unroll
                for (int q = 0; q < 2; q++)
                    mma16816h(cM[p * 2 + q], a4, bf[p][q * 2], bf[p][q * 2 + 1]);
        }
        if (mc + 1 < 16) {
            char* dst = dsm + (s ^ 1) * PV_STG;
            #pragma unroll
            for (int i = 0; i < 2; i++) {
                int idx = tid + i * 256, row = idx >> 3, c16 = idx & 7;
                *(uint4*)(dst + PV_V + row * SPITCH + c16 * 16) = rv[i];
            }
            #pragma unroll
            for (int i = 0; i < 4; i++) {
                int idx = tid + i * 256, row = idx >> 3, c16 = idx & 7;
                *(uint4*)(dst + PV_E + row * SPITCH + c16 * 16) = re[i];
                *(uint4*)(dst + PV_M + row * SPITCH + c16 * 16) = rm[i];
            }
        }
        __syncthreads();
    }

    // epilogue: x = rinv * (cE + esm1 * cM)
    #pragma unroll
    for (int p = 0; p < 4; p++)
        #pragma unroll
        for (int q = 0; q < 2; q++) {
            const int f = p * 2 + q;
            const int d0 = wd * 16 + (lane >> 2);
            const int ncl = wn * 64 + p * 16 + q * 8 + (lane & 3) * 2;
            float r0 = ri[ncl], r1 = ri[ncl + 1];
            float2 lo = {r0 * fmaf(esm1, cM[f][0], cE[f][0]),
                         r1 * fmaf(esm1, cM[f][1], cE[f][1])};
            float2 hi = {r0 * fmaf(esm1, cM[f][2], cE[f][2]),
                         r1 * fmaf(esm1, cM[f][3], cE[f][3])};
            *(float2*)(X + (d0 * HH + h) * N + n0 + ncl) = lo;
            *(float2*)(X + ((d0 + 8) * HH + h) * N + n0 + ncl) = hi;
        }
}

// Merge projection: out = Wm @ (x1 + x2) + bm
__global__ __launch_bounds__(128) void merge_kernel(
    const float* __restrict__ W, const float* __restrict__ bm,
    const float* __restrict__ X1, const float* __restrict__ X2,
    float* __restrict__ O)
{
    __shared__ float As[2][16][64];
    __shared__ float Bs[2][16][132];
    const int tid = threadIdx.x, tx = tid & 15, ty = tid >> 4;
    const int n0 = blockIdx.x * 128, m0 = blockIdx.y * 64;

    ull acc[8][4];
    #pragma unroll
    for (int i = 0; i < 8; i++)
        #pragma unroll
        for (int j = 0; j < 4; j++) acc[i][j] = 0ull;

    const int ao = tid >> 1, ac = (tid & 1) * 8;
    const float* Ap = W + (m0 + ao) * DM + ac;
    const int brow = tid >> 5, bc4 = tid & 31;
    const float* B1 = X1 + brow * N + n0 + bc4 * 4;
    const float* B2 = X2 + brow * N + n0 + bc4 * 4;

    float4 ra0, ra1, rb[4];
    ra0 = *(const float4*)(Ap);
    ra1 = *(const float4*)(Ap + 4);
    #pragma unroll
    for (int i = 0; i < 4; i++) {
        float4 a = *(const float4*)(B1 + (i * 4) * N);
        float4 b = *(const float4*)(B2 + (i * 4) * N);
        rb[i] = make_float4(a.x + b.x, a.y + b.y, a.z + b.z, a.w + b.w);
    }
    {
        As[0][ac + 0][ao] = ra0.x; As[0][ac + 1][ao] = ra0.y;
        As[0][ac + 2][ao] = ra0.z; As[0][ac + 3][ao] = ra0.w;
        As[0][ac + 4][ao] = ra1.x; As[0][ac + 5][ao] = ra1.y;
        As[0][ac + 6][ao] = ra1.z; As[0][ac + 7][ao] = ra1.w;
        #pragma unroll
        for (int i = 0; i < 4; i++)
            *(float4*)&Bs[0][brow + i * 4][bc4 * 4] = rb[i];
    }
    __syncthreads();

    const int KT = DM / 16;
    for (int kt = 0; kt < KT; kt++) {
        const int s = kt & 1;
        if (kt + 1 < KT) {
            const int c0 = (kt + 1) * 16;
            ra0 = *(const float4*)(Ap + c0);
            ra1 = *(const float4*)(Ap + c0 + 4);
            #pragma unroll
            for (int i = 0; i < 4; i++) {
                float4 a = *(const float4*)(B1 + (c0 + i * 4) * N);
                float4 b = *(const float4*)(B2 + (c0 + i * 4) * N);
                rb[i] = make_float4(a.x + b.x, a.y + b.y, a.z + b.z, a.w + b.w);
            }
        }
        gemm16(As[s], Bs[s], acc, tx, ty);
        if (kt + 1 < KT) {
            const int d = s ^ 1;
            As[d][ac + 0][ao] = ra0.x; As[d][ac + 1][ao] = ra0.y;
            As[d][ac + 2][ao] = ra0.z; As[d][ac + 3][ao] = ra0.w;
            As[d][ac + 4][ao] = ra1.x; As[d][ac + 5][ao] = ra1.y;
            As[d][ac + 6][ao] = ra1.z; As[d][ac + 7][ao] = ra1.w;
            #pragma unroll
            for (int i = 0; i < 4; i++)
                *(float4*)&Bs[d][brow + i * 4][bc4 * 4] = rb[i];
        }
        __syncthreads();
    }

    #pragma unroll
    for (int i = 0; i < 8; i++) {
        float bias = bm[m0 + ty * 8 + i];
        float2 v0 = up2(acc[i][0]), v1 = up2(acc[i][1]);
        float2 v2 = up2(acc[i][2]), v3 = up2(acc[i][3]);
        float4 o0 = {v0.x + bias, v0.y + bias, v1.x + bias, v1.y + bias};
        float4 o1 = {v2.x + bias, v2.y + bias, v3.x + bias, v3.y + bias};
        float* row = O + (m0 + ty * 8 + i) * N + n0;
        *(float4*)(row + tx * 4) = o0;
        *(float4*)(row + 64 + tx * 4) = o1;
    }
}

// ---------------- launch ----------------
extern "C" void kernel_launch(void* const* d_in, const int* in_sizes, int n_in,
                              void* d_out, int out_size) {
    const float* query = (const float*)d_in[0];
    const float* key   = (const float*)d_in[1];
    const float* value = (const float*)d_in[2];
    const void*  mask  = d_in[4];
    const float* Wq = (const float*)d_in[5];
    const float* bq = (const float*)d_in[6];
    const float* Wk = (const float*)d_in[7];
    const float* bk = (const float*)d_in[8];
    const float* Wv = (const float*)d_in[9];
    const float* bv = (const float*)d_in[10];
    const float* Wm = (const float*)d_in[11];
    const float* bm = (const float*)d_in[12];
    float* out = (float*)d_out;

    float *qp, *kp, *x1p, *x2p, *Sp;
    us *vhp, *Ehp, *EMhp;
    cudaGetSymbolAddress((void**)&qp, g_q);
    cudaGetSymbolAddress((void**)&kp, g_k);
    cudaGetSymbolAddress((void**)&vhp, g_vh);
    cudaGetSymbolAddress((void**)&x1p, g_x1);
    cudaGetSymbolAddress((void**)&x2p, g_x2);
    cudaGetSymbolAddress((void**)&Sp, g_S);
    cudaGetSymbolAddress((void**)&Ehp, g_Eh);
    cudaGetSymbolAddress((void**)&EMhp, g_EMh);

    cudaFuncSetAttribute(scores_mma_kernel,
                         cudaFuncAttributeMaxDynamicSharedMemorySize, SMTOT);
    cudaFuncSetAttribute(pv_f16_kernel,
                         cudaFuncAttributeMaxDynamicSharedMemorySize, PV_TOT);

    init_kernel<<<1, 1>>>();
    mask_detect_kernel<<<128, 256>>>((const unsigned*)mask);

    qkv_kernel<<<dim3(N / 128, DM / 64, 3), 128>>>(
        Wq, Wk, Wv, bq, bk, bv, query, key, value, qp, kp, vhp);

    scores_mma_kernel<<<dim3(16, 16, HH), 256, SMTOT>>>(
        qp, kp, mask, Sp, Ehp, EMhp);

    rinv_kernel<<<HH * N / 256, 256>>>();
    mean_kernel<<<NN / 256, 256>>>(Sp, mask, out + DM * N);

    pv_f16_kernel<<<dim3(16, 2, HH), 256, PV_TOT>>>(Ehp, EMhp, vhp, x1p, x2p);

    merge_kernel<<<dim3(N / 128, DM / 64), 128>>>(Wm, bm, x1p, x2p, out);
}